// round 1
// baseline (speedup 1.0000x reference)
#include <cuda_runtime.h>
#include <math.h>

#define NBINS   15
#define NTR     20000
#define NTE     10000
#define NBATCH  1024
#define NMC     10000
#define NCLS    10
#define QBLK    128
#define NCHUNK  ((NMC + QBLK - 1) / QBLK)    // 79
#define TS      2048

// BW = 0.3; 2*BW*BW = 0.18; KDE_NORM = 2*pi*BW*BW = 0.565486677646163
// exp(-r2/0.18) = 2^( -r2 * log2(e)/0.18 ).  A = sqrt(log2(e)/0.18)
#define KDE_NORM_F 0.56548667764616278f
#define A_SCALE    2.83107266924078880f   // sqrt(8.014972449383128)

__device__ float  g_tr_rate[NBINS];
__device__ float  g_te_rate[NBINS];
__device__ float  g_cnt;
__device__ double g_partial[NBINS * NCHUNK];

__device__ __forceinline__ float ex2f(float x) {
    float r;
    asm("ex2.approx.ftz.f32 %0, %1;" : "=f"(r) : "f"(x));
    return r;
}

__device__ __forceinline__ float bin_lo(int b) { return (float)b * (1.0f / 15.0f); }
__device__ __forceinline__ float bin_hi(int b) { return (b == NBINS - 1) ? 1.0f : (float)(b + 1) * (1.0f / 15.0f); }

// ---------------------------------------------------------------------------
// Kernel 1: cnt, per-bin train/test rates
// ---------------------------------------------------------------------------
__global__ void ec_prep(const float* __restrict__ train_probs,
                        const float* __restrict__ test_probs,
                        const int*   __restrict__ y,
                        const int*   __restrict__ pred) {
    __shared__ int h_tr[NBINS];
    __shared__ int h_te[NBINS];
    __shared__ int sc;
    int tid = threadIdx.x;
    if (tid < NBINS) { h_tr[tid] = 0; h_te[tid] = 0; }
    if (tid == 0) sc = 0;
    __syncthreads();

    int c = 0;
    for (int i = tid; i < NBATCH; i += blockDim.x) c += (y[i] == pred[i]) ? 1 : 0;
    atomicAdd(&sc, c);

    for (int i = tid; i < NTR; i += blockDim.x) {
        float p = train_probs[i];
        #pragma unroll
        for (int b = 0; b < NBINS; b++)
            if (p > bin_lo(b) && p <= bin_hi(b)) atomicAdd(&h_tr[b], 1);
    }
    for (int i = tid; i < NTE; i += blockDim.x) {
        float p = test_probs[i];
        #pragma unroll
        for (int b = 0; b < NBINS; b++)
            if (p > bin_lo(b) && p <= bin_hi(b)) atomicAdd(&h_te[b], 1);
    }
    __syncthreads();
    if (tid < NBINS) {
        g_tr_rate[tid] = (float)h_tr[tid] * (1.0f / (float)NTR);
        g_te_rate[tid] = (float)h_te[tid] * (1.0f / (float)NTE);
    }
    if (tid == 0) g_cnt = (float)sc;
}

// ---------------------------------------------------------------------------
// Kernel 2: main KDE triple-loop, one thread per MC query
// grid = (NCHUNK, NBINS), block = QBLK
// ---------------------------------------------------------------------------
__global__ __launch_bounds__(QBLK) void ec_main(
    const float2* __restrict__ mc,
    const float2* __restrict__ train_x,
    const float2* __restrict__ test_x,
    const float2* __restrict__ batch_x,
    const int*    __restrict__ y,
    const int*    __restrict__ pred,
    const float*  __restrict__ W,
    const float*  __restrict__ bvec)
{
    __shared__ float2 tile[TS];
    __shared__ float  wsh[NBATCH];
    __shared__ double red[QBLK];

    const int tid = threadIdx.x;
    const int bin = blockIdx.y;
    const int qi  = blockIdx.x * QBLK + tid;
    const bool valid = (qi < NMC);

    float qxr = 1.0e6f, qyr = 1.0e6f;
    if (valid) {
        float2 t = mc[bin * NMC + qi];
        qxr = t.x; qyr = t.y;
    }
    const float qx = qxr * A_SCALE;
    const float qy = qyr * A_SCALE;

    float sb = 0.0f, st = 0.0f, se = 0.0f;

    // ---- batch (weighted) ----
    for (int i = tid; i < NBATCH; i += QBLK) {
        float2 p = batch_x[i];
        tile[i] = make_float2(p.x * A_SCALE, p.y * A_SCALE);
        wsh[i]  = (y[i] == pred[i]) ? 1.0f : 0.0f;
    }
    __syncthreads();
    #pragma unroll 4
    for (int j = 0; j < NBATCH; j++) {
        float2 p = tile[j];
        float dx = qx - p.x, dy = qy - p.y;
        float t = fmaf(dx, -dx, dy * (-dy));
        sb = fmaf(ex2f(t), wsh[j], sb);
    }

    // ---- train ----
    for (int base = 0; base < NTR; base += TS) {
        __syncthreads();
        int n = min(TS, NTR - base);
        for (int i = tid; i < n; i += QBLK) {
            float2 p = train_x[base + i];
            tile[i] = make_float2(p.x * A_SCALE, p.y * A_SCALE);
        }
        __syncthreads();
        #pragma unroll 4
        for (int j = 0; j < n; j++) {
            float2 p = tile[j];
            float dx = qx - p.x, dy = qy - p.y;
            float t = fmaf(dx, -dx, dy * (-dy));
            st += ex2f(t);
        }
    }

    // ---- test ----
    for (int base = 0; base < NTE; base += TS) {
        __syncthreads();
        int n = min(TS, NTE - base);
        for (int i = tid; i < n; i += QBLK) {
            float2 p = test_x[base + i];
            tile[i] = make_float2(p.x * A_SCALE, p.y * A_SCALE);
        }
        __syncthreads();
        #pragma unroll 4
        for (int j = 0; j < n; j++) {
            float2 p = tile[j];
            float dx = qx - p.x, dy = qy - p.y;
            float t = fmaf(dx, -dx, dy * (-dy));
            se += ex2f(t);
        }
    }

    // ---- per-query epilogue ----
    const float cnt     = g_cnt;
    const float tr_rate = g_tr_rate[bin];
    const float te_rate = g_te_rate[bin];

    float kde_tr = st * (1.0f / ((float)NTR * KDE_NORM_F));
    float kde_te = se * (1.0f / ((float)NTE * KDE_NORM_F));
    float kdw    = sb / (fmaxf(cnt, 1.0f) * KDE_NORM_F);
    float p_y    = cnt * (1.0f / (float)NBATCH);

    // softmax max:  logit_c = qx*W[0][c] + qy*W[1][c] + b[c]
    float l[NCLS];
    float m = -1.0e30f;
    #pragma unroll
    for (int c = 0; c < NCLS; c++) {
        l[c] = fmaf(qxr, W[c], fmaf(qyr, W[NCLS + c], bvec[c]));
        m = fmaxf(m, l[c]);
    }
    float ssum = 0.0f;
    #pragma unroll
    for (int c = 0; c < NCLS; c++) ssum += __expf(l[c] - m);
    float hat = 1.0f / ssum;

    float lo = bin_lo(bin), hi = bin_hi(bin);
    float idx = (hat >= lo && hat <= hi) ? 1.0f : 0.0f;

    float d_t = ((te_rate > 0.0f) ? (kde_te / te_rate) : 0.0f) * idx;
    float d_s = ((tr_rate > 0.0f) ? (kde_tr / tr_rate) : 0.0f) * idx;

    float p_hs = kdw * p_y / (kde_tr + 1e-8f);
    p_hs = fminf(fmaxf(p_hs, 0.0f), 1.0f);

    float term = valid ? (p_hs * (d_t - d_s)) : 0.0f;

    red[tid] = (double)term;
    __syncthreads();
    #pragma unroll
    for (int o = QBLK / 2; o > 0; o >>= 1) {
        if (tid < o) red[tid] += red[tid + o];
        __syncthreads();
    }
    if (tid == 0) g_partial[bin * NCHUNK + blockIdx.x] = red[0];
}

// ---------------------------------------------------------------------------
// Kernel 3: fold partials in a fixed order
// ---------------------------------------------------------------------------
__global__ void ec_final(float* __restrict__ out) {
    if (threadIdx.x == 0 && blockIdx.x == 0) {
        double ec = 0.0;
        for (int b = 0; b < NBINS; b++) {
            double s = 0.0;
            for (int c = 0; c < NCHUNK; c++) s += g_partial[b * NCHUNK + c];
            double integral = s * (100.0 / (double)NMC);   // mean * VOLUME
            float te = g_te_rate[b];
            if (te > 0.0f) ec += (double)te * fabs(integral);
        }
        out[0] = (float)ec;
    }
}

// ---------------------------------------------------------------------------
extern "C" void kernel_launch(void* const* d_in, const int* in_sizes, int n_in,
                              void* d_out, int out_size) {
    const float *batch_x = nullptr, *train_probs = nullptr, *test_probs = nullptr;
    const float *train_x = nullptr, *test_x = nullptr, *W = nullptr, *bvec = nullptr, *mc = nullptr;
    const int   *y = nullptr, *pred = nullptr;

    for (int i = 0; i < n_in; i++) {
        int s = in_sizes[i];
        void* p = d_in[i];
        switch (s) {
            case 2048:   batch_x = (const float*)p; break;
            case 1024:   if (!y) y = (const int*)p; else pred = (const int*)p; break;
            case 20000:  if (!train_probs) train_probs = (const float*)p;
                         else test_x = (const float*)p; break;
            case 10000:  test_probs = (const float*)p; break;
            case 40000:  train_x = (const float*)p; break;
            case 20:     W = (const float*)p; break;
            case 10:     bvec = (const float*)p; break;
            case 300000: mc = (const float*)p; break;
            default: break;
        }
    }

    ec_prep<<<1, 256>>>(train_probs, test_probs, y, pred);

    dim3 grid(NCHUNK, NBINS);
    ec_main<<<grid, QBLK>>>((const float2*)mc, (const float2*)train_x,
                            (const float2*)test_x, (const float2*)batch_x,
                            y, pred, W, bvec);

    ec_final<<<1, 32>>>((float*)d_out);
}

// round 2
// speedup vs baseline: 1.2316x; 1.2316x over previous
#include <cuda_runtime.h>
#include <math.h>

#define NBINS   15
#define NTR     20000
#define NTE     10000
#define NBATCH  1024
#define NMC     10000
#define NCLS    10
#define NPTS_TOT (NTR + NTE + NBATCH)

#define GRIDW   16
#define CELLSZ  0.75f
#define INVCELL (1.0f / 0.75f)
#define DOMLO   (-6.0f)
#define RC      2.0f

// c = log2(e)/(2*BW*BW) = log2(e)/0.18
#define CEXP       8.014972449383130f
#define KDE_NORM_F 0.56548667764616278f

#define NQW     313                      // ceil(NMC/32)
#define NSTRIPE 4
#define NTASK   (NBINS * NQW * NSTRIPE)  // 18780
#define NBLKA   (NTASK / 4)              // 4695 (exact)
#define NCHB    79                       // ceil(NMC/128)

__device__ int    g_htr[NBINS], g_hte[NBINS], g_c;
__device__ int    g_hist_p[3][257 * 256];
__device__ int    g_hist_q[NBINS][257 * 256];
__device__ int    g_cs_p[3][257];
__device__ float4 g_spts[NPTS_TOT];
__device__ float4 g_qs[NBINS * NMC];
__device__ float4 g_A[NBINS * NSTRIPE * NMC];
__device__ double g_partial[NBINS * NCHB];

__device__ __forceinline__ float ex2f(float x) {
    float r;
    asm("ex2.approx.ftz.f32 %0, %1;" : "=f"(r) : "f"(x));
    return r;
}
__device__ __forceinline__ float bin_lo(int b) { return (float)b * (1.0f / 15.0f); }
__device__ __forceinline__ float bin_hi(int b) { return (b == NBINS - 1) ? 1.0f : (float)(b + 1) * (1.0f / 15.0f); }

__device__ __forceinline__ int cell_of(float x, float y) {
    int cx = min(max((int)floorf((x - DOMLO) * INVCELL), 0), GRIDW - 1);
    int cy = min(max((int)floorf((y - DOMLO) * INVCELL), 0), GRIDW - 1);
    return cy * GRIDW + cx;
}

// ---------------------------------------------------------------------------
// zero counters
// ---------------------------------------------------------------------------
__global__ void ec_zero() {
    int t = threadIdx.x;
    if (t < NBINS) { g_htr[t] = 0; g_hte[t] = 0; }
    if (t == 0)    g_c = 0;
}

// ---------------------------------------------------------------------------
// rates + cnt (gridded, int atomics -> deterministic)
// ---------------------------------------------------------------------------
__global__ void ec_prep(const float* __restrict__ tp, const float* __restrict__ sp,
                        const int* __restrict__ y, const int* __restrict__ pred) {
    __shared__ int h1[NBINS], h2[NBINS], sc;
    int tid = threadIdx.x;
    if (tid < NBINS) { h1[tid] = 0; h2[tid] = 0; }
    if (tid == 0) sc = 0;
    __syncthreads();

    int gs = gridDim.x * blockDim.x;
    int g  = blockIdx.x * blockDim.x + tid;

    int c = 0;
    for (int i = g; i < NBATCH; i += gs) c += (y[i] == pred[i]) ? 1 : 0;
    atomicAdd(&sc, c);

    for (int i = g; i < NTR; i += gs) {
        float p = tp[i];
        #pragma unroll
        for (int b = 0; b < NBINS; b++)
            if (p > bin_lo(b) && p <= bin_hi(b)) atomicAdd(&h1[b], 1);
    }
    for (int i = g; i < NTE; i += gs) {
        float p = sp[i];
        #pragma unroll
        for (int b = 0; b < NBINS; b++)
            if (p > bin_lo(b) && p <= bin_hi(b)) atomicAdd(&h2[b], 1);
    }
    __syncthreads();
    if (tid < NBINS) {
        if (h1[tid]) atomicAdd(&g_htr[tid], h1[tid]);
        if (h2[tid]) atomicAdd(&g_hte[tid], h2[tid]);
    }
    if (tid == 0 && sc) atomicAdd(&g_c, sc);
}

// ---------------------------------------------------------------------------
// Deterministic stable counting sort into cells.
// blockIdx.x: 0=train 1=test 2=batch(correct only), 3..17 = query bins
// ---------------------------------------------------------------------------
__global__ __launch_bounds__(256) void ec_sort(
    const float2* __restrict__ train, const float2* __restrict__ test,
    const float2* __restrict__ batch, const int* __restrict__ y,
    const int* __restrict__ pred, const float2* __restrict__ mc)
{
    __shared__ int s_tot[257];
    __shared__ int s_cs[258];

    int task = blockIdx.x;
    const float2* src; int N; int* hist; float4* dst;
    bool isq = false, isb = false;
    if      (task == 0) { src = train; N = NTR;    hist = g_hist_p[0]; dst = g_spts; }
    else if (task == 1) { src = test;  N = NTE;    hist = g_hist_p[1]; dst = g_spts + NTR; }
    else if (task == 2) { src = batch; N = NBATCH; hist = g_hist_p[2]; dst = g_spts + NTR + NTE; isb = true; }
    else { int bin = task - 3; src = mc + bin * NMC; N = NMC; hist = g_hist_q[bin]; dst = g_qs + bin * NMC; isq = true; }

    int t = threadIdx.x;
    // zero my histogram column
    for (int c = 0; c < 257; c++) hist[c * 256 + t] = 0;
    __syncthreads();

    int C  = (N + 255) / 256;
    int i0 = t * C, i1 = min(i0 + C, N);

    // pass 1: per-chunk histogram (private column -> no races)
    for (int i = i0; i < i1; i++) {
        float2 p = src[i];
        int c = (isb && (y[i] != pred[i])) ? 256 : cell_of(p.x, p.y);
        hist[c * 256 + t] += 1;
    }
    __syncthreads();

    // pass 2: exclusive prefix over chunks per cell (one warp per 8-strided cell)
    int wid = t >> 5, lane = t & 31;
    for (int c = wid; c < 257; c += 8) {
        int* row = hist + c * 256;
        int v[8];
        #pragma unroll
        for (int j = 0; j < 8; j++) v[j] = row[lane * 8 + j];
        int ls = 0;
        #pragma unroll
        for (int j = 0; j < 8; j++) { int tmp = v[j]; v[j] = ls; ls += tmp; }
        int inc = ls;
        #pragma unroll
        for (int o = 1; o < 32; o <<= 1) {
            int n = __shfl_up_sync(0xffffffffu, inc, o);
            if (lane >= o) inc += n;
        }
        int le = inc - ls;
        #pragma unroll
        for (int j = 0; j < 8; j++) row[lane * 8 + j] = v[j] + le;
        if (lane == 31) s_tot[c] = inc;
    }
    __syncthreads();

    if (t == 0) {
        int run = 0;
        for (int c = 0; c < 256; c++) { s_cs[c] = run; run += s_tot[c]; }
        s_cs[256] = run;
    }
    __syncthreads();
    if (!isq && t <= 256) g_cs_p[task][t] = s_cs[t];

    // pass 3: stable scatter with precompute
    for (int i = i0; i < i1; i++) {
        float2 p = src[i];
        int c = (isb && (y[i] != pred[i])) ? 256 : cell_of(p.x, p.y);
        if (c < 256) {
            int idx = c * 256 + t;
            int r = hist[idx];
            hist[idx] = r + 1;
            int off = s_cs[c] + r;
            float s2 = p.x * p.x + p.y * p.y;
            dst[off] = isq ? make_float4(p.x, p.y, -CEXP * s2, 0.0f)
                           : make_float4(2.0f * CEXP * p.x, 2.0f * CEXP * p.y, -CEXP * s2, 0.0f);
        }
    }
}

// ---------------------------------------------------------------------------
// Phase A: KDE partial sums per (bin, query-warp, stripe)
// ---------------------------------------------------------------------------
__device__ __forceinline__ float kde_span(const float4* __restrict__ pts,
                                          int j0, int j1, float qx, float qy, float qc, float acc)
{
    int j = j0;
    for (; j + 4 <= j1; j += 4) {
        float4 p0 = __ldg(pts + j);
        float4 p1 = __ldg(pts + j + 1);
        float4 p2 = __ldg(pts + j + 2);
        float4 p3 = __ldg(pts + j + 3);
        float t0 = fmaf(p0.x, qx, fmaf(p0.y, qy, p0.z)) + qc;
        float t1 = fmaf(p1.x, qx, fmaf(p1.y, qy, p1.z)) + qc;
        float t2 = fmaf(p2.x, qx, fmaf(p2.y, qy, p2.z)) + qc;
        float t3 = fmaf(p3.x, qx, fmaf(p3.y, qy, p3.z)) + qc;
        acc += ex2f(t0); acc += ex2f(t1); acc += ex2f(t2); acc += ex2f(t3);
    }
    for (; j < j1; j++) {
        float4 p = __ldg(pts + j);
        acc += ex2f(fmaf(p.x, qx, fmaf(p.y, qy, p.z)) + qc);
    }
    return acc;
}

__global__ __launch_bounds__(128) void ec_phaseA()
{
    int wid = threadIdx.x >> 5, lane = threadIdx.x & 31;
    int task = blockIdx.x * 4 + wid;
    int bin = task / (NQW * NSTRIPE);
    int rem = task % (NQW * NSTRIPE);
    int qw = rem >> 2, s = rem & 3;

    int qi = qw * 32 + lane;
    bool valid = qi < NMC;
    float4 q = valid ? g_qs[bin * NMC + qi] : make_float4(0.0f, 0.0f, -1.0e30f, 0.0f);

    float xmn = valid ? q.x : 1.0e30f, xmx = valid ? q.x : -1.0e30f;
    float ymn = valid ? q.y : 1.0e30f, ymx = valid ? q.y : -1.0e30f;
    #pragma unroll
    for (int o = 16; o; o >>= 1) {
        xmn = fminf(xmn, __shfl_xor_sync(0xffffffffu, xmn, o));
        xmx = fmaxf(xmx, __shfl_xor_sync(0xffffffffu, xmx, o));
        ymn = fminf(ymn, __shfl_xor_sync(0xffffffffu, ymn, o));
        ymx = fmaxf(ymx, __shfl_xor_sync(0xffffffffu, ymx, o));
    }

    int cy0 = min(max((int)floorf((ymn - RC - DOMLO) * INVCELL), 0), GRIDW - 1);
    int cy1 = min(max((int)floorf((ymx + RC - DOMLO) * INVCELL), 0), GRIDW - 1);

    float st = 0.0f, se = 0.0f, sb = 0.0f;
    for (int cy = cy0 + ((s - cy0) & 3); cy <= cy1; cy += NSTRIPE) {
        float cyl = DOMLO + cy * CELLSZ, cyh = cyl + CELLSZ;
        float dy = fmaxf(0.0f, fmaxf(cyl - ymx, ymn - cyh));
        float d2 = RC * RC - dy * dy;
        if (d2 <= 0.0f) continue;
        float dx = sqrtf(d2);
        int cx0 = min(max((int)floorf((xmn - dx - DOMLO) * INVCELL), 0), GRIDW - 1);
        int cx1 = min(max((int)floorf((xmx + dx - DOMLO) * INVCELL), 0), GRIDW - 1);
        int ca = cy * GRIDW + cx0, cb = cy * GRIDW + cx1 + 1;

        st = kde_span(g_spts,             g_cs_p[0][ca], g_cs_p[0][cb], q.x, q.y, q.z, st);
        se = kde_span(g_spts + NTR,       g_cs_p[1][ca], g_cs_p[1][cb], q.x, q.y, q.z, se);
        sb = kde_span(g_spts + NTR + NTE, g_cs_p[2][ca], g_cs_p[2][cb], q.x, q.y, q.z, sb);
    }

    if (valid) g_A[(bin * NSTRIPE + s) * NMC + qi] = make_float4(st, se, sb, 0.0f);
}

// ---------------------------------------------------------------------------
// Phase B: fold stripes, epilogue, fixed-slot block reduction
// ---------------------------------------------------------------------------
__global__ __launch_bounds__(128) void ec_phaseB(const float* __restrict__ W,
                                                 const float* __restrict__ bvec)
{
    __shared__ double red[128];
    int tid = threadIdx.x;
    int bin = blockIdx.y;
    int qi  = blockIdx.x * 128 + tid;

    float term = 0.0f;
    if (qi < NMC) {
        float4 q  = g_qs[bin * NMC + qi];
        float4 a0 = g_A[(bin * 4 + 0) * NMC + qi];
        float4 a1 = g_A[(bin * 4 + 1) * NMC + qi];
        float4 a2 = g_A[(bin * 4 + 2) * NMC + qi];
        float4 a3 = g_A[(bin * 4 + 3) * NMC + qi];
        float st = (a0.x + a1.x) + (a2.x + a3.x);
        float se = (a0.y + a1.y) + (a2.y + a3.y);
        float sb = (a0.z + a1.z) + (a2.z + a3.z);

        float cnt     = (float)g_c;
        float tr_rate = (float)g_htr[bin] * (1.0f / (float)NTR);
        float te_rate = (float)g_hte[bin] * (1.0f / (float)NTE);

        float kde_tr = st * (1.0f / ((float)NTR * KDE_NORM_F));
        float kde_te = se * (1.0f / ((float)NTE * KDE_NORM_F));
        float kdw    = sb / (fmaxf(cnt, 1.0f) * KDE_NORM_F);
        float p_y    = cnt * (1.0f / (float)NBATCH);

        float l[NCLS];
        float m = -1.0e30f;
        #pragma unroll
        for (int c = 0; c < NCLS; c++) {
            l[c] = fmaf(q.x, __ldg(W + c), fmaf(q.y, __ldg(W + NCLS + c), __ldg(bvec + c)));
            m = fmaxf(m, l[c]);
        }
        float ssum = 0.0f;
        #pragma unroll
        for (int c = 0; c < NCLS; c++) ssum += __expf(l[c] - m);
        float hat = 1.0f / ssum;

        float lo = bin_lo(bin), hi = bin_hi(bin);
        float idx = (hat >= lo && hat <= hi) ? 1.0f : 0.0f;

        float d_t = ((te_rate > 0.0f) ? (kde_te / te_rate) : 0.0f) * idx;
        float d_s = ((tr_rate > 0.0f) ? (kde_tr / tr_rate) : 0.0f) * idx;

        float p_hs = kdw * p_y / (kde_tr + 1e-8f);
        p_hs = fminf(fmaxf(p_hs, 0.0f), 1.0f);
        term = p_hs * (d_t - d_s);
    }

    red[tid] = (double)term;
    __syncthreads();
    #pragma unroll
    for (int o = 64; o > 0; o >>= 1) {
        if (tid < o) red[tid] += red[tid + o];
        __syncthreads();
    }
    if (tid == 0) g_partial[bin * NCHB + blockIdx.x] = red[0];
}

// ---------------------------------------------------------------------------
__global__ void ec_final(float* __restrict__ out) {
    if (threadIdx.x == 0 && blockIdx.x == 0) {
        double ec = 0.0;
        for (int b = 0; b < NBINS; b++) {
            double s = 0.0;
            for (int c = 0; c < NCHB; c++) s += g_partial[b * NCHB + c];
            double integral = s * (100.0 / (double)NMC);
            float te = (float)g_hte[b] * (1.0f / (float)NTE);
            if (te > 0.0f) ec += (double)te * fabs(integral);
        }
        out[0] = (float)ec;
    }
}

// ---------------------------------------------------------------------------
extern "C" void kernel_launch(void* const* d_in, const int* in_sizes, int n_in,
                              void* d_out, int out_size) {
    const float *batch_x = nullptr, *train_probs = nullptr, *test_probs = nullptr;
    const float *train_x = nullptr, *test_x = nullptr, *W = nullptr, *bvec = nullptr, *mc = nullptr;
    const int   *y = nullptr, *pred = nullptr;

    for (int i = 0; i < n_in; i++) {
        int s = in_sizes[i];
        void* p = d_in[i];
        switch (s) {
            case 2048:   batch_x = (const float*)p; break;
            case 1024:   if (!y) y = (const int*)p; else pred = (const int*)p; break;
            case 20000:  if (!train_probs) train_probs = (const float*)p;
                         else test_x = (const float*)p; break;
            case 10000:  test_probs = (const float*)p; break;
            case 40000:  train_x = (const float*)p; break;
            case 20:     W = (const float*)p; break;
            case 10:     bvec = (const float*)p; break;
            case 300000: mc = (const float*)p; break;
            default: break;
        }
    }

    ec_zero<<<1, 32>>>();
    ec_prep<<<32, 256>>>(train_probs, test_probs, y, pred);
    ec_sort<<<18, 256>>>((const float2*)train_x, (const float2*)test_x,
                         (const float2*)batch_x, y, pred, (const float2*)mc);
    ec_phaseA<<<NBLKA, 128>>>();
    ec_phaseB<<<dim3(NCHB, NBINS), 128>>>(W, bvec);
    ec_final<<<1, 32>>>((float*)d_out);
}

// round 3
// speedup vs baseline: 1.7272x; 1.4024x over previous
#include <cuda_runtime.h>
#include <math.h>

#define NBINS   15
#define NTR     20000
#define NTE     10000
#define NBATCH  1024
#define NMC     10000
#define NCLS    10
#define NPTS_TOT (NTR + NTE + NBATCH)

#define GRIDW   16
#define CELLSZ  0.75f
#define INVCELL (1.0f / 0.75f)
#define DOMLO   (-6.0f)
#define RC      2.0f

// c = log2(e)/(2*BW*BW) = log2(e)/0.18
#define CEXP       8.014972449383130f
#define KDE_NORM_F 0.56548667764616278f

#define NQW     313                      // ceil(NMC/32)
#define NSTRIPE 4
#define NTASK   (NBINS * NQW * NSTRIPE)  // 18780
#define NBLKA   (NTASK / 4)              // 4695
#define NCHB    79                       // ceil(NMC/128)

__device__ int    g_htr[NBINS], g_hte[NBINS], g_c;
__device__ int    g_flag[NBINS * NMC];
__device__ int    g_qn[NBINS];
__device__ int    g_hist_p[3][257 * 256];
__device__ int    g_hist_q[NBINS][257 * 256];
__device__ int    g_cs_p[3][257];
__device__ float4 g_spts[NPTS_TOT];
__device__ float4 g_qs[NBINS * NMC];
__device__ float4 g_A[NBINS * NSTRIPE * NMC];
__device__ double g_partial[NBINS * NCHB];

__device__ __forceinline__ float ex2f(float x) {
    float r;
    asm("ex2.approx.ftz.f32 %0, %1;" : "=f"(r) : "f"(x));
    return r;
}
__device__ __forceinline__ float bin_lo(int b) { return (float)b * (1.0f / 15.0f); }
__device__ __forceinline__ float bin_hi(int b) { return (b == NBINS - 1) ? 1.0f : (float)(b + 1) * (1.0f / 15.0f); }

__device__ __forceinline__ int cell_of(float x, float y) {
    int cx = min(max((int)floorf((x - DOMLO) * INVCELL), 0), GRIDW - 1);
    int cy = min(max((int)floorf((y - DOMLO) * INVCELL), 0), GRIDW - 1);
    return cy * GRIDW + cx;
}
// snake (boustrophedon) cell id: keeps consecutive sorted queries spatially adjacent
__device__ __forceinline__ int cell_of_snake(float x, float y) {
    int cx = min(max((int)floorf((x - DOMLO) * INVCELL), 0), GRIDW - 1);
    int cy = min(max((int)floorf((y - DOMLO) * INVCELL), 0), GRIDW - 1);
    if (cy & 1) cx = GRIDW - 1 - cx;
    return cy * GRIDW + cx;
}

// ---------------------------------------------------------------------------
__global__ void ec_zero() {
    int t = threadIdx.x;
    if (t < NBINS) { g_htr[t] = 0; g_hte[t] = 0; }
    if (t == 0)    g_c = 0;
}

// ---------------------------------------------------------------------------
// Filter: hat = max softmax prob; flag queries whose hat lies in their bin.
// ---------------------------------------------------------------------------
__global__ __launch_bounds__(128) void ec_filter(const float2* __restrict__ mc,
                                                 const float*  __restrict__ W,
                                                 const float*  __restrict__ bvec) {
    int bin = blockIdx.y;
    int qi  = blockIdx.x * 128 + threadIdx.x;
    if (qi >= NMC) return;
    float2 q = mc[bin * NMC + qi];
    float l[NCLS];
    float m = -1.0e30f;
    #pragma unroll
    for (int c = 0; c < NCLS; c++) {
        l[c] = fmaf(q.x, __ldg(W + c), fmaf(q.y, __ldg(W + NCLS + c), __ldg(bvec + c)));
        m = fmaxf(m, l[c]);
    }
    float ssum = 0.0f;
    #pragma unroll
    for (int c = 0; c < NCLS; c++) ssum += __expf(l[c] - m);
    float hat = 1.0f / ssum;
    g_flag[bin * NMC + qi] = (hat >= bin_lo(bin) && hat <= bin_hi(bin)) ? 1 : 0;
}

// ---------------------------------------------------------------------------
// rates + cnt
// ---------------------------------------------------------------------------
__global__ void ec_prep(const float* __restrict__ tp, const float* __restrict__ sp,
                        const int* __restrict__ y, const int* __restrict__ pred) {
    __shared__ int h1[NBINS], h2[NBINS], sc;
    int tid = threadIdx.x;
    if (tid < NBINS) { h1[tid] = 0; h2[tid] = 0; }
    if (tid == 0) sc = 0;
    __syncthreads();

    int gs = gridDim.x * blockDim.x;
    int g  = blockIdx.x * blockDim.x + tid;

    int c = 0;
    for (int i = g; i < NBATCH; i += gs) c += (y[i] == pred[i]) ? 1 : 0;
    atomicAdd(&sc, c);

    for (int i = g; i < NTR; i += gs) {
        float p = tp[i];
        #pragma unroll
        for (int b = 0; b < NBINS; b++)
            if (p > bin_lo(b) && p <= bin_hi(b)) atomicAdd(&h1[b], 1);
    }
    for (int i = g; i < NTE; i += gs) {
        float p = sp[i];
        #pragma unroll
        for (int b = 0; b < NBINS; b++)
            if (p > bin_lo(b) && p <= bin_hi(b)) atomicAdd(&h2[b], 1);
    }
    __syncthreads();
    if (tid < NBINS) {
        if (h1[tid]) atomicAdd(&g_htr[tid], h1[tid]);
        if (h2[tid]) atomicAdd(&g_hte[tid], h2[tid]);
    }
    if (tid == 0 && sc) atomicAdd(&g_c, sc);
}

// ---------------------------------------------------------------------------
// Deterministic stable counting sort into cells.
// task 0=train 1=test 2=batch(correct only); 3..17 = per-bin surviving queries
// ---------------------------------------------------------------------------
__global__ __launch_bounds__(256) void ec_sort(
    const float2* __restrict__ train, const float2* __restrict__ test,
    const float2* __restrict__ batch, const int* __restrict__ y,
    const int* __restrict__ pred, const float2* __restrict__ mc)
{
    __shared__ int s_tot[257];
    __shared__ int s_cs[258];

    int task = blockIdx.x;
    const float2* src; int N; int* hist; float4* dst;
    const int* flags = nullptr;
    bool isq = false, isb = false;
    int bin = 0;
    if      (task == 0) { src = train; N = NTR;    hist = g_hist_p[0]; dst = g_spts; }
    else if (task == 1) { src = test;  N = NTE;    hist = g_hist_p[1]; dst = g_spts + NTR; }
    else if (task == 2) { src = batch; N = NBATCH; hist = g_hist_p[2]; dst = g_spts + NTR + NTE; isb = true; }
    else { bin = task - 3; src = mc + bin * NMC; N = NMC; hist = g_hist_q[bin];
           dst = g_qs + bin * NMC; flags = g_flag + bin * NMC; isq = true; }

    int t = threadIdx.x;
    for (int c = 0; c < 257; c++) hist[c * 256 + t] = 0;
    __syncthreads();

    int C  = (N + 255) / 256;
    int i0 = t * C, i1 = min(i0 + C, N);

    // pass 1: per-chunk histogram
    for (int i = i0; i < i1; i++) {
        float2 p = src[i];
        int c;
        if (isq)      c = flags[i] ? cell_of_snake(p.x, p.y) : 256;
        else if (isb) c = (y[i] != pred[i]) ? 256 : cell_of(p.x, p.y);
        else          c = cell_of(p.x, p.y);
        hist[c * 256 + t] += 1;
    }
    __syncthreads();

    // pass 2: exclusive prefix over chunks per cell
    int wid = t >> 5, lane = t & 31;
    for (int c = wid; c < 257; c += 8) {
        int* row = hist + c * 256;
        int v[8];
        #pragma unroll
        for (int j = 0; j < 8; j++) v[j] = row[lane * 8 + j];
        int ls = 0;
        #pragma unroll
        for (int j = 0; j < 8; j++) { int tmp = v[j]; v[j] = ls; ls += tmp; }
        int inc = ls;
        #pragma unroll
        for (int o = 1; o < 32; o <<= 1) {
            int n = __shfl_up_sync(0xffffffffu, inc, o);
            if (lane >= o) inc += n;
        }
        int le = inc - ls;
        #pragma unroll
        for (int j = 0; j < 8; j++) row[lane * 8 + j] = v[j] + le;
        if (lane == 31) s_tot[c] = inc;
    }
    __syncthreads();

    if (t == 0) {
        int run = 0;
        for (int c = 0; c < 256; c++) { s_cs[c] = run; run += s_tot[c]; }
        s_cs[256] = run;
        if (isq) g_qn[bin] = run;
    }
    __syncthreads();
    if (!isq && t <= 256) g_cs_p[task][t] = s_cs[t];

    // pass 3: stable scatter with precompute
    for (int i = i0; i < i1; i++) {
        float2 p = src[i];
        int c;
        if (isq)      c = flags[i] ? cell_of_snake(p.x, p.y) : 256;
        else if (isb) c = (y[i] != pred[i]) ? 256 : cell_of(p.x, p.y);
        else          c = cell_of(p.x, p.y);
        if (c < 256) {
            int idx = c * 256 + t;
            int r = hist[idx];
            hist[idx] = r + 1;
            int off = s_cs[c] + r;
            float s2 = p.x * p.x + p.y * p.y;
            dst[off] = isq ? make_float4(p.x, p.y, -CEXP * s2, 0.0f)
                           : make_float4(2.0f * CEXP * p.x, 2.0f * CEXP * p.y, -CEXP * s2, 0.0f);
        }
    }
}

// ---------------------------------------------------------------------------
// Phase A: KDE partial sums over surviving queries only
// ---------------------------------------------------------------------------
__device__ __forceinline__ float kde_span(const float4* __restrict__ pts,
                                          int j0, int j1, float qx, float qy, float qc, float acc)
{
    int j = j0;
    for (; j + 4 <= j1; j += 4) {
        float4 p0 = __ldg(pts + j);
        float4 p1 = __ldg(pts + j + 1);
        float4 p2 = __ldg(pts + j + 2);
        float4 p3 = __ldg(pts + j + 3);
        float t0 = fmaf(p0.x, qx, fmaf(p0.y, qy, p0.z)) + qc;
        float t1 = fmaf(p1.x, qx, fmaf(p1.y, qy, p1.z)) + qc;
        float t2 = fmaf(p2.x, qx, fmaf(p2.y, qy, p2.z)) + qc;
        float t3 = fmaf(p3.x, qx, fmaf(p3.y, qy, p3.z)) + qc;
        acc += ex2f(t0); acc += ex2f(t1); acc += ex2f(t2); acc += ex2f(t3);
    }
    for (; j < j1; j++) {
        float4 p = __ldg(pts + j);
        acc += ex2f(fmaf(p.x, qx, fmaf(p.y, qy, p.z)) + qc);
    }
    return acc;
}

__global__ __launch_bounds__(128) void ec_phaseA()
{
    int wid = threadIdx.x >> 5, lane = threadIdx.x & 31;
    int task = blockIdx.x * 4 + wid;
    int bin = task / (NQW * NSTRIPE);
    int rem = task % (NQW * NSTRIPE);
    int qw = rem >> 2, s = rem & 3;

    int qn = g_qn[bin];
    if (qw * 32 >= qn) return;           // warp-uniform early exit

    int qi = qw * 32 + lane;
    bool valid = qi < qn;
    float4 q = valid ? g_qs[bin * NMC + qi] : make_float4(0.0f, 0.0f, -1.0e30f, 0.0f);

    float xmn = valid ? q.x : 1.0e30f, xmx = valid ? q.x : -1.0e30f;
    float ymn = valid ? q.y : 1.0e30f, ymx = valid ? q.y : -1.0e30f;
    #pragma unroll
    for (int o = 16; o; o >>= 1) {
        xmn = fminf(xmn, __shfl_xor_sync(0xffffffffu, xmn, o));
        xmx = fmaxf(xmx, __shfl_xor_sync(0xffffffffu, xmx, o));
        ymn = fminf(ymn, __shfl_xor_sync(0xffffffffu, ymn, o));
        ymx = fmaxf(ymx, __shfl_xor_sync(0xffffffffu, ymx, o));
    }

    int cy0 = min(max((int)floorf((ymn - RC - DOMLO) * INVCELL), 0), GRIDW - 1);
    int cy1 = min(max((int)floorf((ymx + RC - DOMLO) * INVCELL), 0), GRIDW - 1);

    float st = 0.0f, se = 0.0f, sb = 0.0f;
    for (int cy = cy0 + ((s - cy0) & 3); cy <= cy1; cy += NSTRIPE) {
        float cyl = DOMLO + cy * CELLSZ, cyh = cyl + CELLSZ;
        float dy = fmaxf(0.0f, fmaxf(cyl - ymx, ymn - cyh));
        float d2 = RC * RC - dy * dy;
        if (d2 <= 0.0f) continue;
        float dx = sqrtf(d2);
        int cx0 = min(max((int)floorf((xmn - dx - DOMLO) * INVCELL), 0), GRIDW - 1);
        int cx1 = min(max((int)floorf((xmx + dx - DOMLO) * INVCELL), 0), GRIDW - 1);
        int ca = cy * GRIDW + cx0, cb = cy * GRIDW + cx1 + 1;

        st = kde_span(g_spts,             g_cs_p[0][ca], g_cs_p[0][cb], q.x, q.y, q.z, st);
        se = kde_span(g_spts + NTR,       g_cs_p[1][ca], g_cs_p[1][cb], q.x, q.y, q.z, se);
        sb = kde_span(g_spts + NTR + NTE, g_cs_p[2][ca], g_cs_p[2][cb], q.x, q.y, q.z, sb);
    }

    if (valid) g_A[(bin * NSTRIPE + s) * NMC + qi] = make_float4(st, se, sb, 0.0f);
}

// ---------------------------------------------------------------------------
// Phase B: fold stripes + epilogue (idx == 1 for all survivors)
// ---------------------------------------------------------------------------
__global__ __launch_bounds__(128) void ec_phaseB()
{
    __shared__ double red[128];
    int tid = threadIdx.x;
    int bin = blockIdx.y;
    int k   = blockIdx.x * 128 + tid;

    float term = 0.0f;
    if (k < g_qn[bin]) {
        float4 a0 = g_A[(bin * 4 + 0) * NMC + k];
        float4 a1 = g_A[(bin * 4 + 1) * NMC + k];
        float4 a2 = g_A[(bin * 4 + 2) * NMC + k];
        float4 a3 = g_A[(bin * 4 + 3) * NMC + k];
        float st = (a0.x + a1.x) + (a2.x + a3.x);
        float se = (a0.y + a1.y) + (a2.y + a3.y);
        float sb = (a0.z + a1.z) + (a2.z + a3.z);

        float cnt     = (float)g_c;
        float tr_rate = (float)g_htr[bin] * (1.0f / (float)NTR);
        float te_rate = (float)g_hte[bin] * (1.0f / (float)NTE);

        float kde_tr = st * (1.0f / ((float)NTR * KDE_NORM_F));
        float kde_te = se * (1.0f / ((float)NTE * KDE_NORM_F));
        float kdw    = sb / (fmaxf(cnt, 1.0f) * KDE_NORM_F);
        float p_y    = cnt * (1.0f / (float)NBATCH);

        float d_t = (te_rate > 0.0f) ? (kde_te / te_rate) : 0.0f;
        float d_s = (tr_rate > 0.0f) ? (kde_tr / tr_rate) : 0.0f;

        float p_hs = kdw * p_y / (kde_tr + 1e-8f);
        p_hs = fminf(fmaxf(p_hs, 0.0f), 1.0f);
        term = p_hs * (d_t - d_s);
    }

    red[tid] = (double)term;
    __syncthreads();
    #pragma unroll
    for (int o = 64; o > 0; o >>= 1) {
        if (tid < o) red[tid] += red[tid + o];
        __syncthreads();
    }
    if (tid == 0) g_partial[bin * NCHB + blockIdx.x] = red[0];
}

// ---------------------------------------------------------------------------
__global__ void ec_final(float* __restrict__ out) {
    if (threadIdx.x == 0 && blockIdx.x == 0) {
        double ec = 0.0;
        for (int b = 0; b < NBINS; b++) {
            double s = 0.0;
            for (int c = 0; c < NCHB; c++) s += g_partial[b * NCHB + c];
            double integral = s * (100.0 / (double)NMC);
            float te = (float)g_hte[b] * (1.0f / (float)NTE);
            if (te > 0.0f) ec += (double)te * fabs(integral);
        }
        out[0] = (float)ec;
    }
}

// ---------------------------------------------------------------------------
extern "C" void kernel_launch(void* const* d_in, const int* in_sizes, int n_in,
                              void* d_out, int out_size) {
    const float *batch_x = nullptr, *train_probs = nullptr, *test_probs = nullptr;
    const float *train_x = nullptr, *test_x = nullptr, *W = nullptr, *bvec = nullptr, *mc = nullptr;
    const int   *y = nullptr, *pred = nullptr;

    for (int i = 0; i < n_in; i++) {
        int s = in_sizes[i];
        void* p = d_in[i];
        switch (s) {
            case 2048:   batch_x = (const float*)p; break;
            case 1024:   if (!y) y = (const int*)p; else pred = (const int*)p; break;
            case 20000:  if (!train_probs) train_probs = (const float*)p;
                         else test_x = (const float*)p; break;
            case 10000:  test_probs = (const float*)p; break;
            case 40000:  train_x = (const float*)p; break;
            case 20:     W = (const float*)p; break;
            case 10:     bvec = (const float*)p; break;
            case 300000: mc = (const float*)p; break;
            default: break;
        }
    }

    ec_zero<<<1, 32>>>();
    ec_filter<<<dim3(NCHB, NBINS), 128>>>((const float2*)mc, W, bvec);
    ec_prep<<<32, 256>>>(train_probs, test_probs, y, pred);
    ec_sort<<<18, 256>>>((const float2*)train_x, (const float2*)test_x,
                         (const float2*)batch_x, y, pred, (const float2*)mc);
    ec_phaseA<<<NBLKA, 128>>>();
    ec_phaseB<<<dim3(NCHB, NBINS), 128>>>();
    ec_final<<<1, 32>>>((float*)d_out);
}

// round 4
// speedup vs baseline: 1.9256x; 1.1149x over previous
#include <cuda_runtime.h>
#include <math.h>

#define NBINS   15
#define NTR     20000
#define NTE     10000
#define NBATCH  1024
#define NMC     10000
#define NCLS    10
#define NPTS_TOT (NTR + NTE + NBATCH)

#define GRIDW   16
#define CELLSZ  0.75f
#define INVCELL (1.0f / 0.75f)
#define DOMLO   (-6.0f)
#define RC      2.0f

#define CEXP       8.014972449383130f
#define KDE_NORM_F 0.56548667764616278f

#define NQW     313
#define NSTRIPE 4
#define NTASK   (NBINS * NQW * NSTRIPE)  // 18780
#define NBLKA   296
#define NWARPSA (NBLKA * 4)              // 1184 persistent warps
#define NCHB    79

#define STHREADS 256
#define SWARPS   8

__device__ int    g_htr[NBINS], g_hte[NBINS], g_c;
__device__ int    g_flag[NBINS * NMC];
__device__ int    g_qn[NBINS];
__device__ int    g_cs_p[3][257];
__device__ float4 g_spts[NPTS_TOT];
__device__ float4 g_qs[NBINS * NMC];
__device__ float4 g_A[NBINS * NSTRIPE * NMC];
__device__ double g_partial[NBINS * NCHB];

__device__ __forceinline__ float ex2f(float x) {
    float r;
    asm("ex2.approx.ftz.f32 %0, %1;" : "=f"(r) : "f"(x));
    return r;
}
__device__ __forceinline__ float bin_lo(int b) { return (float)b * (1.0f / 15.0f); }
__device__ __forceinline__ float bin_hi(int b) { return (b == NBINS - 1) ? 1.0f : (float)(b + 1) * (1.0f / 15.0f); }

__device__ __forceinline__ int cell_of(float x, float y) {
    int cx = min(max((int)floorf((x - DOMLO) * INVCELL), 0), GRIDW - 1);
    int cy = min(max((int)floorf((y - DOMLO) * INVCELL), 0), GRIDW - 1);
    return cy * GRIDW + cx;
}
__device__ __forceinline__ int cell_of_snake(float x, float y) {
    int cx = min(max((int)floorf((x - DOMLO) * INVCELL), 0), GRIDW - 1);
    int cy = min(max((int)floorf((y - DOMLO) * INVCELL), 0), GRIDW - 1);
    if (cy & 1) cx = GRIDW - 1 - cx;
    return cy * GRIDW + cx;
}

// ---------------------------------------------------------------------------
// Prep: single block, writes rates + cnt (no prior zero needed)
// ---------------------------------------------------------------------------
__global__ __launch_bounds__(1024) void ec_prep(const float* __restrict__ tp,
                                                const float* __restrict__ sp,
                                                const int* __restrict__ y,
                                                const int* __restrict__ pred) {
    __shared__ int h1[NBINS], h2[NBINS], sc;
    int t = threadIdx.x;
    if (t < NBINS) { h1[t] = 0; h2[t] = 0; }
    if (t == 0) sc = 0;
    __syncthreads();

    int c = 0;
    for (int i = t; i < NBATCH; i += 1024) c += (y[i] == pred[i]) ? 1 : 0;
    #pragma unroll
    for (int o = 16; o; o >>= 1) c += __shfl_xor_sync(0xffffffffu, c, o);
    if ((t & 31) == 0 && c) atomicAdd(&sc, c);

    for (int i = t; i < NTR; i += 1024) {
        float p = tp[i];
        #pragma unroll
        for (int b = 0; b < NBINS; b++)
            if (p > bin_lo(b) && p <= bin_hi(b)) atomicAdd(&h1[b], 1);
    }
    for (int i = t; i < NTE; i += 1024) {
        float p = sp[i];
        #pragma unroll
        for (int b = 0; b < NBINS; b++)
            if (p > bin_lo(b) && p <= bin_hi(b)) atomicAdd(&h2[b], 1);
    }
    __syncthreads();
    if (t < NBINS) { g_htr[t] = h1[t]; g_hte[t] = h2[t]; }
    if (t == 0) g_c = sc;
}

// ---------------------------------------------------------------------------
// Filter: flag queries whose max-softmax lies in their bin
// ---------------------------------------------------------------------------
__global__ __launch_bounds__(128) void ec_filter(const float2* __restrict__ mc,
                                                 const float*  __restrict__ W,
                                                 const float*  __restrict__ bvec) {
    int bin = blockIdx.y;
    int qi  = blockIdx.x * 128 + threadIdx.x;
    if (qi >= NMC) return;
    float2 q = mc[bin * NMC + qi];
    float l[NCLS];
    float m = -1.0e30f;
    #pragma unroll
    for (int c = 0; c < NCLS; c++) {
        l[c] = fmaf(q.x, __ldg(W + c), fmaf(q.y, __ldg(W + NCLS + c), __ldg(bvec + c)));
        m = fmaxf(m, l[c]);
    }
    float ssum = 0.0f;
    #pragma unroll
    for (int c = 0; c < NCLS; c++) ssum += __expf(l[c] - m);
    float hat = 1.0f / ssum;
    g_flag[bin * NMC + qi] = (hat >= bin_lo(bin) && hat <= bin_hi(bin)) ? 1 : 0;
}

// ---------------------------------------------------------------------------
// Deterministic stable counting sort, smem histogram + warp-aggregated counts
// task 0=train 1=test 2=batch(correct only); 3..17 = per-bin surviving queries
// ---------------------------------------------------------------------------
__global__ __launch_bounds__(STHREADS) void ec_sort(
    const float2* __restrict__ train, const float2* __restrict__ test,
    const float2* __restrict__ batch, const int* __restrict__ y,
    const int* __restrict__ pred, const float2* __restrict__ mc)
{
    __shared__ int hist[257 * SWARPS];   // per (cell, warp) counts / offsets
    __shared__ int s_tot[257];
    __shared__ int s_cs[258];

    int task = blockIdx.x;
    const float2* src; int N; float4* dst;
    const int* flags = nullptr;
    bool isq = false, isb = false;
    int bin = 0;
    if      (task == 0) { src = train; N = NTR;    dst = g_spts; }
    else if (task == 1) { src = test;  N = NTE;    dst = g_spts + NTR; }
    else if (task == 2) { src = batch; N = NBATCH; dst = g_spts + NTR + NTE; isb = true; }
    else { bin = task - 3; src = mc + bin * NMC; N = NMC;
           dst = g_qs + bin * NMC; flags = g_flag + bin * NMC; isq = true; }

    int t = threadIdx.x, w = t >> 5, lane = t & 31;
    unsigned lmask = (1u << lane) - 1u;

    for (int i = t; i < 257 * SWARPS; i += STHREADS) hist[i] = 0;
    __syncthreads();

    int iters = (N + STHREADS - 1) / STHREADS;

    // pass 1: warp-aggregated histogram, coalesced order (k, warp, lane)
    for (int k = 0; k < iters; k++) {
        int i = k * STHREADS + t;
        int c = 256;
        if (i < N) {
            float2 p = src[i];
            if (isq)      c = flags[i] ? cell_of_snake(p.x, p.y) : 256;
            else if (isb) c = (y[i] != pred[i]) ? 256 : cell_of(p.x, p.y);
            else          c = cell_of(p.x, p.y);
        }
        unsigned m = __match_any_sync(0xffffffffu, c);
        int leader = __ffs(m) - 1;
        if (lane == leader) hist[c * SWARPS + w] += __popc(m);
    }
    __syncthreads();

    // pass 2: within-cell exclusive over warps + cell totals
    for (int c = w; c < 257; c += SWARPS) {
        int v = (lane < SWARPS) ? hist[c * SWARPS + lane] : 0;
        int incl = v;
        #pragma unroll
        for (int o = 1; o < SWARPS; o <<= 1) {
            int n = __shfl_up_sync(0xffffffffu, incl, o);
            if (lane >= o) incl += n;
        }
        if (lane < SWARPS) hist[c * SWARPS + lane] = incl - v;
        if (lane == SWARPS - 1) s_tot[c] = incl;
    }
    __syncthreads();
    if (t == 0) {
        int run = 0;
        for (int c = 0; c < 256; c++) { s_cs[c] = run; run += s_tot[c]; }
        s_cs[256] = run;
        if (isq) g_qn[bin] = run;
    }
    __syncthreads();
    if (!isq) {
        if (t < 256) g_cs_p[task][t] = s_cs[t];
        if (t == 0)  g_cs_p[task][256] = s_cs[256];
    }

    // pass 3: stable scatter (same traversal order)
    for (int k = 0; k < iters; k++) {
        int i = k * STHREADS + t;
        int c = 256;
        float2 p = make_float2(0.0f, 0.0f);
        if (i < N) {
            p = src[i];
            if (isq)      c = flags[i] ? cell_of_snake(p.x, p.y) : 256;
            else if (isb) c = (y[i] != pred[i]) ? 256 : cell_of(p.x, p.y);
            else          c = cell_of(p.x, p.y);
        }
        unsigned m = __match_any_sync(0xffffffffu, c);
        int leader = __ffs(m) - 1;
        int r = 0;
        if (lane == leader) {
            r = hist[c * SWARPS + w];
            hist[c * SWARPS + w] = r + __popc(m);
        }
        r = __shfl_sync(0xffffffffu, r, leader);
        if (c < 256) {
            int off = s_cs[c] + r + __popc(m & lmask);
            float s2 = p.x * p.x + p.y * p.y;
            dst[off] = isq ? make_float4(p.x, p.y, -CEXP * s2, 0.0f)
                           : make_float4(2.0f * CEXP * p.x, 2.0f * CEXP * p.y, -CEXP * s2, 0.0f);
        }
    }
}

// ---------------------------------------------------------------------------
// Phase A: persistent warps loop over (bin, query-warp, stripe) tasks
// ---------------------------------------------------------------------------
__device__ __forceinline__ float kde_span(const float4* __restrict__ pts,
                                          int j0, int j1, float qx, float qy, float qc, float acc)
{
    int j = j0;
    for (; j + 4 <= j1; j += 4) {
        float4 p0 = __ldg(pts + j);
        float4 p1 = __ldg(pts + j + 1);
        float4 p2 = __ldg(pts + j + 2);
        float4 p3 = __ldg(pts + j + 3);
        float t0 = fmaf(p0.x, qx, fmaf(p0.y, qy, p0.z)) + qc;
        float t1 = fmaf(p1.x, qx, fmaf(p1.y, qy, p1.z)) + qc;
        float t2 = fmaf(p2.x, qx, fmaf(p2.y, qy, p2.z)) + qc;
        float t3 = fmaf(p3.x, qx, fmaf(p3.y, qy, p3.z)) + qc;
        acc += ex2f(t0); acc += ex2f(t1); acc += ex2f(t2); acc += ex2f(t3);
    }
    for (; j < j1; j++) {
        float4 p = __ldg(pts + j);
        acc += ex2f(fmaf(p.x, qx, fmaf(p.y, qy, p.z)) + qc);
    }
    return acc;
}

__global__ __launch_bounds__(128) void ec_phaseA()
{
    int lane = threadIdx.x & 31;
    int wg   = blockIdx.x * 4 + (threadIdx.x >> 5);

    for (int task = wg; task < NTASK; task += NWARPSA) {
        int bin = task / (NQW * NSTRIPE);
        int rem = task % (NQW * NSTRIPE);
        int qw = rem >> 2, s = rem & 3;

        int qn = g_qn[bin];
        if (qw * 32 >= qn) continue;

        int qi = qw * 32 + lane;
        bool valid = qi < qn;
        float4 q = valid ? g_qs[bin * NMC + qi] : make_float4(0.0f, 0.0f, -1.0e30f, 0.0f);

        float xmn = valid ? q.x : 1.0e30f, xmx = valid ? q.x : -1.0e30f;
        float ymn = valid ? q.y : 1.0e30f, ymx = valid ? q.y : -1.0e30f;
        #pragma unroll
        for (int o = 16; o; o >>= 1) {
            xmn = fminf(xmn, __shfl_xor_sync(0xffffffffu, xmn, o));
            xmx = fmaxf(xmx, __shfl_xor_sync(0xffffffffu, xmx, o));
            ymn = fminf(ymn, __shfl_xor_sync(0xffffffffu, ymn, o));
            ymx = fmaxf(ymx, __shfl_xor_sync(0xffffffffu, ymx, o));
        }

        int cy0 = min(max((int)floorf((ymn - RC - DOMLO) * INVCELL), 0), GRIDW - 1);
        int cy1 = min(max((int)floorf((ymx + RC - DOMLO) * INVCELL), 0), GRIDW - 1);

        float st = 0.0f, se = 0.0f, sb = 0.0f;
        for (int cy = cy0 + ((s - cy0) & 3); cy <= cy1; cy += NSTRIPE) {
            float cyl = DOMLO + cy * CELLSZ, cyh = cyl + CELLSZ;
            float dy = fmaxf(0.0f, fmaxf(cyl - ymx, ymn - cyh));
            float d2 = RC * RC - dy * dy;
            if (d2 <= 0.0f) continue;
            float dx = sqrtf(d2);
            int cx0 = min(max((int)floorf((xmn - dx - DOMLO) * INVCELL), 0), GRIDW - 1);
            int cx1 = min(max((int)floorf((xmx + dx - DOMLO) * INVCELL), 0), GRIDW - 1);
            int ca = cy * GRIDW + cx0, cb = cy * GRIDW + cx1 + 1;

            st = kde_span(g_spts,             g_cs_p[0][ca], g_cs_p[0][cb], q.x, q.y, q.z, st);
            se = kde_span(g_spts + NTR,       g_cs_p[1][ca], g_cs_p[1][cb], q.x, q.y, q.z, se);
            sb = kde_span(g_spts + NTR + NTE, g_cs_p[2][ca], g_cs_p[2][cb], q.x, q.y, q.z, sb);
        }

        if (valid) g_A[(bin * NSTRIPE + s) * NMC + qi] = make_float4(st, se, sb, 0.0f);
    }
}

// ---------------------------------------------------------------------------
// Phase B: fold stripes + epilogue; fixed-slot block reduction
// ---------------------------------------------------------------------------
__global__ __launch_bounds__(128) void ec_phaseB()
{
    __shared__ double red[128];
    int tid = threadIdx.x;
    int bin = blockIdx.y;
    int k   = blockIdx.x * 128 + tid;

    float term = 0.0f;
    if (k < g_qn[bin]) {
        float4 a0 = g_A[(bin * 4 + 0) * NMC + k];
        float4 a1 = g_A[(bin * 4 + 1) * NMC + k];
        float4 a2 = g_A[(bin * 4 + 2) * NMC + k];
        float4 a3 = g_A[(bin * 4 + 3) * NMC + k];
        float st = (a0.x + a1.x) + (a2.x + a3.x);
        float se = (a0.y + a1.y) + (a2.y + a3.y);
        float sb = (a0.z + a1.z) + (a2.z + a3.z);

        float cnt     = (float)g_c;
        float tr_rate = (float)g_htr[bin] * (1.0f / (float)NTR);
        float te_rate = (float)g_hte[bin] * (1.0f / (float)NTE);

        float kde_tr = st * (1.0f / ((float)NTR * KDE_NORM_F));
        float kde_te = se * (1.0f / ((float)NTE * KDE_NORM_F));
        float kdw    = sb / (fmaxf(cnt, 1.0f) * KDE_NORM_F);
        float p_y    = cnt * (1.0f / (float)NBATCH);

        float d_t = (te_rate > 0.0f) ? (kde_te / te_rate) : 0.0f;
        float d_s = (tr_rate > 0.0f) ? (kde_tr / tr_rate) : 0.0f;

        float p_hs = kdw * p_y / (kde_tr + 1e-8f);
        p_hs = fminf(fmaxf(p_hs, 0.0f), 1.0f);
        term = p_hs * (d_t - d_s);
    }

    red[tid] = (double)term;
    __syncthreads();
    #pragma unroll
    for (int o = 64; o > 0; o >>= 1) {
        if (tid < o) red[tid] += red[tid + o];
        __syncthreads();
    }
    if (tid == 0) g_partial[bin * NCHB + blockIdx.x] = red[0];
}

// ---------------------------------------------------------------------------
// Final: warp per bin, parallel fold
// ---------------------------------------------------------------------------
__global__ __launch_bounds__(512) void ec_final(float* __restrict__ out) {
    __shared__ double sbin[16];
    int t = threadIdx.x, w = t >> 5, lane = t & 31;
    if (w < NBINS) {
        double s = 0.0;
        for (int c = lane; c < NCHB; c += 32) s += g_partial[w * NCHB + c];
        #pragma unroll
        for (int o = 16; o; o >>= 1) s += __shfl_xor_sync(0xffffffffu, s, o);
        if (lane == 0) {
            double integral = s * (100.0 / (double)NMC);
            float te = (float)g_hte[w] * (1.0f / (float)NTE);
            sbin[w] = (te > 0.0f) ? (double)te * fabs(integral) : 0.0;
        }
    }
    __syncthreads();
    if (t == 0) {
        double ec = 0.0;
        for (int b = 0; b < NBINS; b++) ec += sbin[b];
        out[0] = (float)ec;
    }
}

// ---------------------------------------------------------------------------
extern "C" void kernel_launch(void* const* d_in, const int* in_sizes, int n_in,
                              void* d_out, int out_size) {
    const float *batch_x = nullptr, *train_probs = nullptr, *test_probs = nullptr;
    const float *train_x = nullptr, *test_x = nullptr, *W = nullptr, *bvec = nullptr, *mc = nullptr;
    const int   *y = nullptr, *pred = nullptr;

    for (int i = 0; i < n_in; i++) {
        int s = in_sizes[i];
        void* p = d_in[i];
        switch (s) {
            case 2048:   batch_x = (const float*)p; break;
            case 1024:   if (!y) y = (const int*)p; else pred = (const int*)p; break;
            case 20000:  if (!train_probs) train_probs = (const float*)p;
                         else test_x = (const float*)p; break;
            case 10000:  test_probs = (const float*)p; break;
            case 40000:  train_x = (const float*)p; break;
            case 20:     W = (const float*)p; break;
            case 10:     bvec = (const float*)p; break;
            case 300000: mc = (const float*)p; break;
            default: break;
        }
    }

    ec_prep<<<1, 1024>>>(train_probs, test_probs, y, pred);
    ec_filter<<<dim3(NCHB, NBINS), 128>>>((const float2*)mc, W, bvec);
    ec_sort<<<18, STHREADS>>>((const float2*)train_x, (const float2*)test_x,
                              (const float2*)batch_x, y, pred, (const float2*)mc);
    ec_phaseA<<<NBLKA, 128>>>();
    ec_phaseB<<<dim3(NCHB, NBINS), 128>>>();
    ec_final<<<1, 512>>>((float*)d_out);
}

// round 5
// speedup vs baseline: 3.9012x; 2.0260x over previous
#include <cuda_runtime.h>
#include <math.h>

#define NBINS   15
#define NTR     20000
#define NTE     10000
#define NBATCH  1024
#define NMC     10000
#define NCLS    10
#define NPTS_TOT (NTR + NTE + NBATCH)

#define GRIDW   16
#define CELLSZ  0.75f
#define INVCELL (1.0f / 0.75f)
#define DOMLO   (-6.0f)
#define RC      2.0f

#define CEXP       8.014972449383130f
#define KDE_NORM_F 0.56548667764616278f

#define NQWMAX  704          // >= 2*NMC/32 + NBINS (boundary double-count safe)
#define NSLOT   64           // point-chunk slots per query warp
#define CHPTS   512          // points per task chunk; 64*512 > NPTS_TOT
#define POPCH   8            // tasks popped per atomic
#define NBLKA   592
#define NCHB    79

#define STHREADS 256
#define SWARPS   8

__device__ int    g_htr[NBINS], g_hte[NBINS], g_c;
__device__ int    g_qn[NBINS];
__device__ int    g_cs_p[3][257];
__device__ int    g_wq_bin[NQWMAX];
__device__ int    g_wq_first[NBINS];
__device__ int    g_nqw_tot, g_ntask, g_task_ctr;
__device__ float4 g_spts[NPTS_TOT];
__device__ float4 g_qs[NBINS * NMC];
__device__ float4 g_A[NSLOT][NQWMAX * 32];     // ~23 MB, fixed slots
__device__ double g_partial[NBINS * NCHB];

__device__ __forceinline__ float ex2f(float x) {
    float r;
    asm("ex2.approx.ftz.f32 %0, %1;" : "=f"(r) : "f"(x));
    return r;
}
__device__ __forceinline__ float bin_lo(int b) { return (float)b * (1.0f / 15.0f); }
__device__ __forceinline__ float bin_hi(int b) { return (b == NBINS - 1) ? 1.0f : (float)(b + 1) * (1.0f / 15.0f); }

__device__ __forceinline__ int cell_of(float x, float y) {
    int cx = min(max((int)floorf((x - DOMLO) * INVCELL), 0), GRIDW - 1);
    int cy = min(max((int)floorf((y - DOMLO) * INVCELL), 0), GRIDW - 1);
    return cy * GRIDW + cx;
}
__device__ __forceinline__ int cell_of_snake(float x, float y) {
    int cx = min(max((int)floorf((x - DOMLO) * INVCELL), 0), GRIDW - 1);
    int cy = min(max((int)floorf((y - DOMLO) * INVCELL), 0), GRIDW - 1);
    if (cy & 1) cx = GRIDW - 1 - cx;
    return cy * GRIDW + cx;
}

// ---------------------------------------------------------------------------
// Prep: single block — rates + cnt
// ---------------------------------------------------------------------------
__global__ __launch_bounds__(1024) void ec_prep(const float* __restrict__ tp,
                                                const float* __restrict__ sp,
                                                const int* __restrict__ y,
                                                const int* __restrict__ pred) {
    __shared__ int h1[NBINS], h2[NBINS], sc;
    int t = threadIdx.x;
    if (t < NBINS) { h1[t] = 0; h2[t] = 0; }
    if (t == 0) sc = 0;
    __syncthreads();

    int c = 0;
    for (int i = t; i < NBATCH; i += 1024) c += (y[i] == pred[i]) ? 1 : 0;
    #pragma unroll
    for (int o = 16; o; o >>= 1) c += __shfl_xor_sync(0xffffffffu, c, o);
    if ((t & 31) == 0 && c) atomicAdd(&sc, c);

    for (int i = t; i < NTR; i += 1024) {
        float p = tp[i];
        #pragma unroll
        for (int b = 0; b < NBINS; b++)
            if (p > bin_lo(b) && p <= bin_hi(b)) atomicAdd(&h1[b], 1);
    }
    for (int i = t; i < NTE; i += 1024) {
        float p = sp[i];
        #pragma unroll
        for (int b = 0; b < NBINS; b++)
            if (p > bin_lo(b) && p <= bin_hi(b)) atomicAdd(&h2[b], 1);
    }
    __syncthreads();
    if (t < NBINS) { g_htr[t] = h1[t]; g_hte[t] = h2[t]; }
    if (t == 0) g_c = sc;
}

// ---------------------------------------------------------------------------
// Deterministic stable counting sort into cells, with inline softmax filter
// for the query tasks. task 0=train 1=test 2=batch; 3..17 = query bins.
// ---------------------------------------------------------------------------
__global__ __launch_bounds__(STHREADS) void ec_sort(
    const float2* __restrict__ train, const float2* __restrict__ test,
    const float2* __restrict__ batch, const int* __restrict__ y,
    const int* __restrict__ pred, const float2* __restrict__ mc,
    const float* __restrict__ W, const float* __restrict__ bvec)
{
    __shared__ int  hist[257 * SWARPS];
    __shared__ int  s_tot[257];
    __shared__ int  s_cs[258];
    __shared__ unsigned char s_flag[NMC];

    int task = blockIdx.x;
    const float2* src; int N; float4* dst;
    bool isq = false, isb = false;
    int bin = 0;
    if      (task == 0) { src = train; N = NTR;    dst = g_spts; }
    else if (task == 1) { src = test;  N = NTE;    dst = g_spts + NTR; }
    else if (task == 2) { src = batch; N = NBATCH; dst = g_spts + NTR + NTE; isb = true; }
    else { bin = task - 3; src = mc + bin * NMC; N = NMC; dst = g_qs + bin * NMC; isq = true; }

    int t = threadIdx.x, w = t >> 5, lane = t & 31;
    unsigned lmask = (1u << lane) - 1u;

    for (int i = t; i < 257 * SWARPS; i += STHREADS) hist[i] = 0;
    __syncthreads();

    int iters = (N + STHREADS - 1) / STHREADS;
    float blo = bin_lo(bin), bhi = bin_hi(bin);

    // pass 1: warp-aggregated histogram (+ inline filter for queries)
    for (int k = 0; k < iters; k++) {
        int i = k * STHREADS + t;
        int c = 256;
        if (i < N) {
            float2 p = src[i];
            if (isq) {
                float l[NCLS];
                float m = -1.0e30f;
                #pragma unroll
                for (int cc = 0; cc < NCLS; cc++) {
                    l[cc] = fmaf(p.x, __ldg(W + cc), fmaf(p.y, __ldg(W + NCLS + cc), __ldg(bvec + cc)));
                    m = fmaxf(m, l[cc]);
                }
                float ssum = 0.0f;
                #pragma unroll
                for (int cc = 0; cc < NCLS; cc++) ssum += __expf(l[cc] - m);
                float hat = 1.0f / ssum;
                int f = (hat >= blo && hat <= bhi) ? 1 : 0;
                s_flag[i] = (unsigned char)f;
                c = f ? cell_of_snake(p.x, p.y) : 256;
            }
            else if (isb) c = (y[i] != pred[i]) ? 256 : cell_of(p.x, p.y);
            else          c = cell_of(p.x, p.y);
        }
        unsigned m = __match_any_sync(0xffffffffu, c);
        int leader = __ffs(m) - 1;
        if (lane == leader) hist[c * SWARPS + w] += __popc(m);
    }
    __syncthreads();

    // pass 2: exclusive over warps per cell + cell totals
    for (int c = w; c < 257; c += SWARPS) {
        int v = (lane < SWARPS) ? hist[c * SWARPS + lane] : 0;
        int incl = v;
        #pragma unroll
        for (int o = 1; o < SWARPS; o <<= 1) {
            int n = __shfl_up_sync(0xffffffffu, incl, o);
            if (lane >= o) incl += n;
        }
        if (lane < SWARPS) hist[c * SWARPS + lane] = incl - v;
        if (lane == SWARPS - 1) s_tot[c] = incl;
    }
    __syncthreads();
    if (t == 0) {
        int run = 0;
        for (int c = 0; c < 256; c++) { s_cs[c] = run; run += s_tot[c]; }
        s_cs[256] = run;
        if (isq) g_qn[bin] = run;
    }
    __syncthreads();
    if (!isq) {
        if (t < 256) g_cs_p[task][t] = s_cs[t];
        if (t == 0)  g_cs_p[task][256] = s_cs[256];
    }

    // pass 3: stable scatter (same traversal order)
    for (int k = 0; k < iters; k++) {
        int i = k * STHREADS + t;
        int c = 256;
        float2 p = make_float2(0.0f, 0.0f);
        if (i < N) {
            p = src[i];
            if (isq)      c = s_flag[i] ? cell_of_snake(p.x, p.y) : 256;
            else if (isb) c = (y[i] != pred[i]) ? 256 : cell_of(p.x, p.y);
            else          c = cell_of(p.x, p.y);
        }
        unsigned m = __match_any_sync(0xffffffffu, c);
        int leader = __ffs(m) - 1;
        int r = 0;
        if (lane == leader) {
            r = hist[c * SWARPS + w];
            hist[c * SWARPS + w] = r + __popc(m);
        }
        r = __shfl_sync(0xffffffffu, r, leader);
        if (c < 256) {
            int off = s_cs[c] + r + __popc(m & lmask);
            float s2 = p.x * p.x + p.y * p.y;
            dst[off] = isq ? make_float4(p.x, p.y, -CEXP * s2, 0.0f)
                           : make_float4(2.0f * CEXP * p.x, 2.0f * CEXP * p.y, -CEXP * s2, 0.0f);
        }
    }
}

// ---------------------------------------------------------------------------
// Plan: warp map, task count, reset pop counter
// ---------------------------------------------------------------------------
__global__ __launch_bounds__(256) void ec_plan() {
    __shared__ int first[NBINS + 1];
    int t = threadIdx.x;
    if (t == 0) {
        int run = 0;
        for (int b = 0; b < NBINS; b++) {
            first[b] = run;
            g_wq_first[b] = run;
            run += (g_qn[b] + 31) / 32;
        }
        first[NBINS] = run;
        g_nqw_tot  = run;
        g_ntask    = run * NSLOT;
        g_task_ctr = 0;
    }
    __syncthreads();
    int tot = first[NBINS];
    for (int wq = t; wq < tot; wq += 256) {
        int b = 0;
        while (b < NBINS - 1 && wq >= first[b + 1]) b++;
        g_wq_bin[wq] = b;
    }
}

// ---------------------------------------------------------------------------
// Phase A: dynamic work-stealing over uniform point-chunk tasks
// ---------------------------------------------------------------------------
__device__ __forceinline__ float kde_span(const float4* __restrict__ pts,
                                          int j0, int j1, float qx, float qy, float qc, float acc)
{
    int j = j0;
    for (; j + 4 <= j1; j += 4) {
        float4 p0 = __ldg(pts + j);
        float4 p1 = __ldg(pts + j + 1);
        float4 p2 = __ldg(pts + j + 2);
        float4 p3 = __ldg(pts + j + 3);
        float t0 = fmaf(p0.x, qx, fmaf(p0.y, qy, p0.z)) + qc;
        float t1 = fmaf(p1.x, qx, fmaf(p1.y, qy, p1.z)) + qc;
        float t2 = fmaf(p2.x, qx, fmaf(p2.y, qy, p2.z)) + qc;
        float t3 = fmaf(p3.x, qx, fmaf(p3.y, qy, p3.z)) + qc;
        acc += ex2f(t0); acc += ex2f(t1); acc += ex2f(t2); acc += ex2f(t3);
    }
    for (; j < j1; j++) {
        float4 p = __ldg(pts + j);
        acc += ex2f(fmaf(p.x, qx, fmaf(p.y, qy, p.z)) + qc);
    }
    return acc;
}

__global__ __launch_bounds__(128) void ec_phaseA()
{
    const int lane = threadIdx.x & 31;
    const int ntask = g_ntask;

    int   cached_qw = -1;
    int   cy0 = 0, cy1 = -1;
    float qx = 0.0f, qy = 0.0f, qc = -1.0e30f;
    float xmn = 0, xmx = 0, ymn = 0, ymx = 0;

    while (true) {
        int t0 = 0;
        if (lane == 0) t0 = atomicAdd(&g_task_ctr, POPCH);
        t0 = __shfl_sync(0xffffffffu, t0, 0);
        if (t0 >= ntask) return;
        int t1 = min(t0 + POPCH, ntask);

        for (int tk = t0; tk < t1; tk++) {
            int qw = tk >> 6, slot = tk & (NSLOT - 1);

            if (qw != cached_qw) {
                cached_qw = qw;
                int bin = g_wq_bin[qw];
                int lqw = qw - g_wq_first[bin];
                int qn  = g_qn[bin];
                int qi  = lqw * 32 + lane;
                bool valid = qi < qn;
                float4 q = valid ? g_qs[bin * NMC + qi] : make_float4(0.0f, 0.0f, -1.0e30f, 0.0f);
                qx = q.x; qy = q.y; qc = q.z;
                xmn = valid ? q.x : 1.0e30f; xmx = valid ? q.x : -1.0e30f;
                ymn = valid ? q.y : 1.0e30f; ymx = valid ? q.y : -1.0e30f;
                #pragma unroll
                for (int o = 16; o; o >>= 1) {
                    xmn = fminf(xmn, __shfl_xor_sync(0xffffffffu, xmn, o));
                    xmx = fmaxf(xmx, __shfl_xor_sync(0xffffffffu, xmx, o));
                    ymn = fminf(ymn, __shfl_xor_sync(0xffffffffu, ymn, o));
                    ymx = fmaxf(ymx, __shfl_xor_sync(0xffffffffu, ymx, o));
                }
                cy0 = min(max((int)floorf((ymn - RC - DOMLO) * INVCELL), 0), GRIDW - 1);
                cy1 = min(max((int)floorf((ymx + RC - DOMLO) * INVCELL), 0), GRIDW - 1);
            }

            // walk the concatenated span stream; process [lo,hi) point window
            int lo = slot * CHPTS, hi = lo + CHPTS;
            int pos = 0;
            float st = 0.0f, se = 0.0f, sb = 0.0f;

            for (int cy = cy0; cy <= cy1 && pos < hi; cy++) {
                float cyl = DOMLO + cy * CELLSZ, cyh = cyl + CELLSZ;
                float dyv = fmaxf(0.0f, fmaxf(cyl - ymx, ymn - cyh));
                float d2 = RC * RC - dyv * dyv;
                if (d2 <= 0.0f) continue;
                float dxv = sqrtf(d2);
                int cx0 = min(max((int)floorf((xmn - dxv - DOMLO) * INVCELL), 0), GRIDW - 1);
                int cx1 = min(max((int)floorf((xmx + dxv - DOMLO) * INVCELL), 0), GRIDW - 1);
                int ca = cy * GRIDW + cx0, cb = cy * GRIDW + cx1 + 1;

                #pragma unroll
                for (int d = 0; d < 3; d++) {
                    int j0 = g_cs_p[d][ca], j1 = g_cs_p[d][cb];
                    int L = j1 - j0;
                    int a = max(lo - pos, 0), b = min(hi - pos, L);
                    if (b > a) {
                        const float4* base = (d == 0) ? g_spts
                                           : (d == 1) ? (g_spts + NTR)
                                                      : (g_spts + NTR + NTE);
                        float acc = kde_span(base, j0 + a, j0 + b, qx, qy, qc, 0.0f);
                        if (d == 0) st += acc; else if (d == 1) se += acc; else sb += acc;
                    }
                    pos += L;
                }
            }

            g_A[slot][qw * 32 + lane] = make_float4(st, se, sb, 0.0f);
        }
    }
}

// ---------------------------------------------------------------------------
// Phase B: fold slots in fixed order + epilogue + fixed-slot reduction
// ---------------------------------------------------------------------------
__global__ __launch_bounds__(128) void ec_phaseB()
{
    __shared__ double red[128];
    int tid = threadIdx.x;
    int bin = blockIdx.y;
    int k   = blockIdx.x * 128 + tid;

    float term = 0.0f;
    if (k < g_qn[bin]) {
        int gqi = g_wq_first[bin] * 32 + k;
        float st = 0.0f, se = 0.0f, sb = 0.0f;
        #pragma unroll
        for (int s = 0; s < NSLOT; s++) {
            float4 a = g_A[s][gqi];
            st += a.x; se += a.y; sb += a.z;
        }

        float cnt     = (float)g_c;
        float tr_rate = (float)g_htr[bin] * (1.0f / (float)NTR);
        float te_rate = (float)g_hte[bin] * (1.0f / (float)NTE);

        float kde_tr = st * (1.0f / ((float)NTR * KDE_NORM_F));
        float kde_te = se * (1.0f / ((float)NTE * KDE_NORM_F));
        float kdw    = sb / (fmaxf(cnt, 1.0f) * KDE_NORM_F);
        float p_y    = cnt * (1.0f / (float)NBATCH);

        float d_t = (te_rate > 0.0f) ? (kde_te / te_rate) : 0.0f;
        float d_s = (tr_rate > 0.0f) ? (kde_tr / tr_rate) : 0.0f;

        float p_hs = kdw * p_y / (kde_tr + 1e-8f);
        p_hs = fminf(fmaxf(p_hs, 0.0f), 1.0f);
        term = p_hs * (d_t - d_s);
    }

    red[tid] = (double)term;
    __syncthreads();
    #pragma unroll
    for (int o = 64; o > 0; o >>= 1) {
        if (tid < o) red[tid] += red[tid + o];
        __syncthreads();
    }
    if (tid == 0) g_partial[bin * NCHB + blockIdx.x] = red[0];
}

// ---------------------------------------------------------------------------
__global__ __launch_bounds__(512) void ec_final(float* __restrict__ out) {
    __shared__ double sbin[16];
    int t = threadIdx.x, w = t >> 5, lane = t & 31;
    if (w < NBINS) {
        double s = 0.0;
        for (int c = lane; c < NCHB; c += 32) s += g_partial[w * NCHB + c];
        #pragma unroll
        for (int o = 16; o; o >>= 1) s += __shfl_xor_sync(0xffffffffu, s, o);
        if (lane == 0) {
            double integral = s * (100.0 / (double)NMC);
            float te = (float)g_hte[w] * (1.0f / (float)NTE);
            sbin[w] = (te > 0.0f) ? (double)te * fabs(integral) : 0.0;
        }
    }
    __syncthreads();
    if (t == 0) {
        double ec = 0.0;
        for (int b = 0; b < NBINS; b++) ec += sbin[b];
        out[0] = (float)ec;
    }
}

// ---------------------------------------------------------------------------
extern "C" void kernel_launch(void* const* d_in, const int* in_sizes, int n_in,
                              void* d_out, int out_size) {
    const float *batch_x = nullptr, *train_probs = nullptr, *test_probs = nullptr;
    const float *train_x = nullptr, *test_x = nullptr, *W = nullptr, *bvec = nullptr, *mc = nullptr;
    const int   *y = nullptr, *pred = nullptr;

    for (int i = 0; i < n_in; i++) {
        int s = in_sizes[i];
        void* p = d_in[i];
        switch (s) {
            case 2048:   batch_x = (const float*)p; break;
            case 1024:   if (!y) y = (const int*)p; else pred = (const int*)p; break;
            case 20000:  if (!train_probs) train_probs = (const float*)p;
                         else test_x = (const float*)p; break;
            case 10000:  test_probs = (const float*)p; break;
            case 40000:  train_x = (const float*)p; break;
            case 20:     W = (const float*)p; break;
            case 10:     bvec = (const float*)p; break;
            case 300000: mc = (const float*)p; break;
            default: break;
        }
    }

    ec_prep<<<1, 1024>>>(train_probs, test_probs, y, pred);
    ec_sort<<<18, STHREADS>>>((const float2*)train_x, (const float2*)test_x,
                              (const float2*)batch_x, y, pred, (const float2*)mc, W, bvec);
    ec_plan<<<1, 256>>>();
    ec_phaseA<<<NBLKA, 128>>>();
    ec_phaseB<<<dim3(NCHB, NBINS), 128>>>();
    ec_final<<<1, 512>>>((float*)d_out);
}

// round 7
// speedup vs baseline: 6.3077x; 1.6169x over previous
#include <cuda_runtime.h>
#include <math.h>

#define NBINS   15
#define NTR     20000
#define NTE     10000
#define NBATCH  1024
#define NMC     10000
#define NCLS    10
#define NPTS_TOT (NTR + NTE + NBATCH)

#define GRIDW   16
#define CELLSZ  0.75f
#define INVCELL (1.0f / 0.75f)
#define DOMLO   (-6.0f)
#define RC      2.0f

#define CEXP       8.014972449383130f
#define KDE_NORM_F 0.56548667764616278f

#define NQWMAX  704
#define NSLOT   64           // CHPTS*NSLOT >= NPTS_TOT
#define CHPTS   512
#define NBLKA   592
#define NCHB    79
#define MAXROWS 16

#define STHREADS 512
#define SWARPS   16

__device__ int    g_htr[NBINS], g_hte[NBINS], g_c;
__device__ int    g_qn[NBINS];
__device__ int    g_cs_p[3][257];
__device__ int    g_wq_bin[NQWMAX];
__device__ int    g_wq_first[NBINS];
__device__ int    g_nqw_tot, g_ntask, g_task_ctr;
__device__ int    g_qw_span[NQWMAX];
__device__ int    g_qw_nrows[NQWMAX];
__device__ int4   g_qw_rowA[NQWMAX * MAXROWS];   // {cum, jtr0, jte0, jb0}
__device__ int4   g_qw_rowB[NQWMAX * MAXROWS];   // {Ltr, Lte, Lb, 0}
__device__ float4 g_spts[NPTS_TOT];
__device__ float4 g_qs[NBINS * NMC];
__device__ float4 g_A[NSLOT][NQWMAX * 32];
__device__ double g_partial[NBINS * NCHB];

__device__ __forceinline__ float ex2f(float x) {
    float r;
    asm("ex2.approx.ftz.f32 %0, %1;" : "=f"(r) : "f"(x));
    return r;
}
__device__ __forceinline__ float bin_lo(int b) { return (float)b * (1.0f / 15.0f); }
__device__ __forceinline__ float bin_hi(int b) { return (b == NBINS - 1) ? 1.0f : (float)(b + 1) * (1.0f / 15.0f); }

__device__ __forceinline__ int cell_of(float x, float y) {
    int cx = min(max((int)floorf((x - DOMLO) * INVCELL), 0), GRIDW - 1);
    int cy = min(max((int)floorf((y - DOMLO) * INVCELL), 0), GRIDW - 1);
    return cy * GRIDW + cx;
}
__device__ __forceinline__ int cell_of_snake(float x, float y) {
    int cx = min(max((int)floorf((x - DOMLO) * INVCELL), 0), GRIDW - 1);
    int cy = min(max((int)floorf((y - DOMLO) * INVCELL), 0), GRIDW - 1);
    if (cy & 1) cx = GRIDW - 1 - cx;
    return cy * GRIDW + cx;
}

// ---------------------------------------------------------------------------
// Prep: single block — rates + cnt
// ---------------------------------------------------------------------------
__global__ __launch_bounds__(1024) void ec_prep(const float* __restrict__ tp,
                                                const float* __restrict__ sp,
                                                const int* __restrict__ y,
                                                const int* __restrict__ pred) {
    __shared__ int h1[NBINS], h2[NBINS], sc;
    int t = threadIdx.x;
    if (t < NBINS) { h1[t] = 0; h2[t] = 0; }
    if (t == 0) sc = 0;
    __syncthreads();

    int c = 0;
    for (int i = t; i < NBATCH; i += 1024) c += (y[i] == pred[i]) ? 1 : 0;
    #pragma unroll
    for (int o = 16; o; o >>= 1) c += __shfl_xor_sync(0xffffffffu, c, o);
    if ((t & 31) == 0 && c) atomicAdd(&sc, c);

    for (int i = t; i < NTR; i += 1024) {
        float p = tp[i];
        #pragma unroll
        for (int b = 0; b < NBINS; b++)
            if (p > bin_lo(b) && p <= bin_hi(b)) atomicAdd(&h1[b], 1);
    }
    for (int i = t; i < NTE; i += 1024) {
        float p = sp[i];
        #pragma unroll
        for (int b = 0; b < NBINS; b++)
            if (p > bin_lo(b) && p <= bin_hi(b)) atomicAdd(&h2[b], 1);
    }
    __syncthreads();
    if (t < NBINS) { g_htr[t] = h1[t]; g_hte[t] = h2[t]; }
    if (t == 0) g_c = sc;
}

// ---------------------------------------------------------------------------
// Deterministic stable counting sort + inline softmax filter for queries
// ---------------------------------------------------------------------------
__global__ __launch_bounds__(STHREADS) void ec_sort(
    const float2* __restrict__ train, const float2* __restrict__ test,
    const float2* __restrict__ batch, const int* __restrict__ y,
    const int* __restrict__ pred, const float2* __restrict__ mc,
    const float* __restrict__ W, const float* __restrict__ bvec)
{
    __shared__ int  hist[257 * SWARPS];
    __shared__ int  s_tot[257];
    __shared__ int  s_cs[258];
    __shared__ unsigned char s_flag[NMC];

    int task = blockIdx.x;
    const float2* src; int N; float4* dst;
    bool isq = false, isb = false;
    int bin = 0;
    if      (task == 0) { src = train; N = NTR;    dst = g_spts; }
    else if (task == 1) { src = test;  N = NTE;    dst = g_spts + NTR; }
    else if (task == 2) { src = batch; N = NBATCH; dst = g_spts + NTR + NTE; isb = true; }
    else { bin = task - 3; src = mc + bin * NMC; N = NMC; dst = g_qs + bin * NMC; isq = true; }

    int t = threadIdx.x, w = t >> 5, lane = t & 31;
    unsigned lmask = (1u << lane) - 1u;

    for (int i = t; i < 257 * SWARPS; i += STHREADS) hist[i] = 0;
    __syncthreads();

    int iters = (N + STHREADS - 1) / STHREADS;
    float blo = bin_lo(bin), bhi = bin_hi(bin);

    for (int k = 0; k < iters; k++) {
        int i = k * STHREADS + t;
        int c = 256;
        if (i < N) {
            float2 p = src[i];
            if (isq) {
                float l[NCLS];
                float m = -1.0e30f;
                #pragma unroll
                for (int cc = 0; cc < NCLS; cc++) {
                    l[cc] = fmaf(p.x, __ldg(W + cc), fmaf(p.y, __ldg(W + NCLS + cc), __ldg(bvec + cc)));
                    m = fmaxf(m, l[cc]);
                }
                float ssum = 0.0f;
                #pragma unroll
                for (int cc = 0; cc < NCLS; cc++) ssum += __expf(l[cc] - m);
                float hat = 1.0f / ssum;
                int f = (hat >= blo && hat <= bhi) ? 1 : 0;
                s_flag[i] = (unsigned char)f;
                c = f ? cell_of_snake(p.x, p.y) : 256;
            }
            else if (isb) c = (y[i] != pred[i]) ? 256 : cell_of(p.x, p.y);
            else          c = cell_of(p.x, p.y);
        }
        unsigned m = __match_any_sync(0xffffffffu, c);
        int leader = __ffs(m) - 1;
        if (lane == leader) hist[c * SWARPS + w] += __popc(m);
    }
    __syncthreads();

    for (int c = w; c < 257; c += SWARPS) {
        int v = (lane < SWARPS) ? hist[c * SWARPS + lane] : 0;
        int incl = v;
        #pragma unroll
        for (int o = 1; o < SWARPS; o <<= 1) {
            int n = __shfl_up_sync(0xffffffffu, incl, o);
            if (lane >= o) incl += n;
        }
        if (lane < SWARPS) hist[c * SWARPS + lane] = incl - v;
        if (lane == SWARPS - 1) s_tot[c] = incl;
    }
    __syncthreads();
    if (t == 0) {
        int run = 0;
        for (int c = 0; c < 256; c++) { s_cs[c] = run; run += s_tot[c]; }
        s_cs[256] = run;
        if (isq) g_qn[bin] = run;
    }
    __syncthreads();
    if (!isq) {
        if (t < 256) g_cs_p[task][t] = s_cs[t];
        if (t == 0)  g_cs_p[task][256] = s_cs[256];
    }

    for (int k = 0; k < iters; k++) {
        int i = k * STHREADS + t;
        int c = 256;
        float2 p = make_float2(0.0f, 0.0f);
        if (i < N) {
            p = src[i];
            if (isq)      c = s_flag[i] ? cell_of_snake(p.x, p.y) : 256;
            else if (isb) c = (y[i] != pred[i]) ? 256 : cell_of(p.x, p.y);
            else          c = cell_of(p.x, p.y);
        }
        unsigned m = __match_any_sync(0xffffffffu, c);
        int leader = __ffs(m) - 1;
        int r = 0;
        if (lane == leader) {
            r = hist[c * SWARPS + w];
            hist[c * SWARPS + w] = r + __popc(m);
        }
        r = __shfl_sync(0xffffffffu, r, leader);
        if (c < 256) {
            int off = s_cs[c] + r + __popc(m & lmask);
            float s2 = p.x * p.x + p.y * p.y;
            dst[off] = isq ? make_float4(p.x, p.y, -CEXP * s2, 0.0f)
                           : make_float4(2.0f * CEXP * p.x, 2.0f * CEXP * p.y, -CEXP * s2, 0.0f);
        }
    }
}

// ---------------------------------------------------------------------------
// Plan 1: warp map + counter reset
// ---------------------------------------------------------------------------
__global__ __launch_bounds__(256) void ec_plan() {
    __shared__ int first[NBINS + 1];
    int t = threadIdx.x;
    if (t == 0) {
        int run = 0;
        for (int b = 0; b < NBINS; b++) {
            first[b] = run;
            g_wq_first[b] = run;
            run += (g_qn[b] + 31) / 32;
        }
        first[NBINS] = run;
        g_nqw_tot  = run;
        g_ntask    = run * NSLOT;
        g_task_ctr = 0;
    }
    __syncthreads();
    int tot = first[NBINS];
    for (int wq = t; wq < tot; wq += 256) {
        int b = 0;
        while (b < NBINS - 1 && wq >= first[b + 1]) b++;
        g_wq_bin[wq] = b;
    }
}

// ---------------------------------------------------------------------------
// Plan 2: per query-warp geometry — bbox, pruned rows, span descriptors
// ---------------------------------------------------------------------------
__global__ __launch_bounds__(32) void ec_plan2() {
    int qw = blockIdx.x;
    if (qw >= g_nqw_tot) return;
    int lane = threadIdx.x;

    int bin = g_wq_bin[qw];
    int lqw = qw - g_wq_first[bin];
    int qn  = g_qn[bin];
    int qi  = lqw * 32 + lane;
    bool valid = qi < qn;
    float4 q = valid ? g_qs[bin * NMC + qi] : make_float4(0.0f, 0.0f, 0.0f, 0.0f);

    float xmn = valid ? q.x : 1.0e30f, xmx = valid ? q.x : -1.0e30f;
    float ymn = valid ? q.y : 1.0e30f, ymx = valid ? q.y : -1.0e30f;
    #pragma unroll
    for (int o = 16; o; o >>= 1) {
        xmn = fminf(xmn, __shfl_xor_sync(0xffffffffu, xmn, o));
        xmx = fmaxf(xmx, __shfl_xor_sync(0xffffffffu, xmx, o));
        ymn = fminf(ymn, __shfl_xor_sync(0xffffffffu, ymn, o));
        ymx = fmaxf(ymx, __shfl_xor_sync(0xffffffffu, ymx, o));
    }

    if (lane == 0) {
        int cy0 = min(max((int)floorf((ymn - RC - DOMLO) * INVCELL), 0), GRIDW - 1);
        int cy1 = min(max((int)floorf((ymx + RC - DOMLO) * INVCELL), 0), GRIDW - 1);
        int cum = 0, nr = 0;
        for (int cy = cy0; cy <= cy1; cy++) {
            float cyl = DOMLO + cy * CELLSZ, cyh = cyl + CELLSZ;
            float dyv = fmaxf(0.0f, fmaxf(cyl - ymx, ymn - cyh));
            float d2 = RC * RC - dyv * dyv;
            if (d2 <= 0.0f) continue;
            float dxv = sqrtf(d2);
            int cx0 = min(max((int)floorf((xmn - dxv - DOMLO) * INVCELL), 0), GRIDW - 1);
            int cx1 = min(max((int)floorf((xmx + dxv - DOMLO) * INVCELL), 0), GRIDW - 1);
            int ca = cy * GRIDW + cx0, cb = cy * GRIDW + cx1 + 1;
            int jtr0 = g_cs_p[0][ca], Ltr = g_cs_p[0][cb] - jtr0;
            int jte0 = g_cs_p[1][ca], Lte = g_cs_p[1][cb] - jte0;
            int jb0  = g_cs_p[2][ca], Lb  = g_cs_p[2][cb] - jb0;
            if (Ltr + Lte + Lb > 0) {
                g_qw_rowA[qw * MAXROWS + nr] = make_int4(cum, jtr0, jte0, jb0);
                g_qw_rowB[qw * MAXROWS + nr] = make_int4(Ltr, Lte, Lb, 0);
                cum += Ltr + Lte + Lb;
                nr++;
            }
        }
        g_qw_nrows[qw] = nr;
        g_qw_span[qw]  = cum;
    }
}

// ---------------------------------------------------------------------------
// Phase A: fine-grained dynamic stealing over precomputed span chunks
// ---------------------------------------------------------------------------
__device__ __forceinline__ float kde_span(const float4* __restrict__ pts,
                                          int j0, int j1, float qx, float qy, float qc, float acc)
{
    int j = j0;
    for (; j + 4 <= j1; j += 4) {
        float4 p0 = __ldg(pts + j);
        float4 p1 = __ldg(pts + j + 1);
        float4 p2 = __ldg(pts + j + 2);
        float4 p3 = __ldg(pts + j + 3);
        float t0 = fmaf(p0.x, qx, fmaf(p0.y, qy, p0.z)) + qc;
        float t1 = fmaf(p1.x, qx, fmaf(p1.y, qy, p1.z)) + qc;
        float t2 = fmaf(p2.x, qx, fmaf(p2.y, qy, p2.z)) + qc;
        float t3 = fmaf(p3.x, qx, fmaf(p3.y, qy, p3.z)) + qc;
        acc += ex2f(t0); acc += ex2f(t1); acc += ex2f(t2); acc += ex2f(t3);
    }
    for (; j < j1; j++) {
        float4 p = __ldg(pts + j);
        acc += ex2f(fmaf(p.x, qx, fmaf(p.y, qy, p.z)) + qc);
    }
    return acc;
}

__global__ __launch_bounds__(128) void ec_phaseA()
{
    const int lane = threadIdx.x & 31;
    const int ntask = g_ntask;

    int   cached_qw = -1;
    float qx = 0.0f, qy = 0.0f, qc = -1.0e30f;

    while (true) {
        int tk = 0;
        if (lane == 0) tk = atomicAdd(&g_task_ctr, 1);
        tk = __shfl_sync(0xffffffffu, tk, 0);
        if (tk >= ntask) return;

        int qw = tk >> 6, slot = tk & (NSLOT - 1);
        int span = g_qw_span[qw];
        int lo = slot * CHPTS;
        if (lo >= span) continue;
        int hi = min(lo + CHPTS, span);

        if (qw != cached_qw) {
            cached_qw = qw;
            int bin = g_wq_bin[qw];
            int lqw = qw - g_wq_first[bin];
            int qn  = g_qn[bin];
            int qi  = lqw * 32 + lane;
            bool valid = qi < qn;
            float4 q = valid ? g_qs[bin * NMC + qi] : make_float4(0.0f, 0.0f, -1.0e30f, 0.0f);
            qx = q.x; qy = q.y; qc = q.z;
        }

        int nrows = g_qw_nrows[qw];
        float st = 0.0f, se = 0.0f, sb = 0.0f;

        for (int r = 0; r < nrows; r++) {
            int4 A = g_qw_rowA[qw * MAXROWS + r];
            if (A.x >= hi) break;
            int4 B = g_qw_rowB[qw * MAXROWS + r];
            int rowEnd = A.x + B.x + B.y + B.z;
            if (rowEnd <= lo) continue;

            int seg0 = A.x;
            // train
            {
                int a = max(lo - seg0, 0), b = min(hi - seg0, B.x);
                if (b > a) st = kde_span(g_spts, A.y + a, A.y + b, qx, qy, qc, st);
                seg0 += B.x;
            }
            // test
            {
                int a = max(lo - seg0, 0), b = min(hi - seg0, B.y);
                if (b > a) se = kde_span(g_spts + NTR, A.z + a, A.z + b, qx, qy, qc, se);
                seg0 += B.y;
            }
            // batch
            {
                int a = max(lo - seg0, 0), b = min(hi - seg0, B.z);
                if (b > a) sb = kde_span(g_spts + NTR + NTE, A.w + a, A.w + b, qx, qy, qc, sb);
            }
        }

        g_A[slot][qw * 32 + lane] = make_float4(st, se, sb, 0.0f);
    }
}

// ---------------------------------------------------------------------------
// Phase B: fold slots in fixed order + epilogue + fixed-slot reduction
// ---------------------------------------------------------------------------
__global__ __launch_bounds__(128) void ec_phaseB()
{
    __shared__ double red[128];
    int tid = threadIdx.x;
    int bin = blockIdx.y;
    int k   = blockIdx.x * 128 + tid;

    float term = 0.0f;
    if (k < g_qn[bin]) {
        int qw  = g_wq_first[bin] + (k >> 5);
        int gqi = qw * 32 + (k & 31);
        int nslots = min((g_qw_span[qw] + CHPTS - 1) / CHPTS, NSLOT);
        float st = 0.0f, se = 0.0f, sb = 0.0f;
        for (int s = 0; s < nslots; s++) {
            float4 a = g_A[s][gqi];
            st += a.x; se += a.y; sb += a.z;
        }

        float cnt     = (float)g_c;
        float tr_rate = (float)g_htr[bin] * (1.0f / (float)NTR);
        float te_rate = (float)g_hte[bin] * (1.0f / (float)NTE);

        float kde_tr = st * (1.0f / ((float)NTR * KDE_NORM_F));
        float kde_te = se * (1.0f / ((float)NTE * KDE_NORM_F));
        float kdw    = sb / (fmaxf(cnt, 1.0f) * KDE_NORM_F);
        float p_y    = cnt * (1.0f / (float)NBATCH);

        float d_t = (te_rate > 0.0f) ? (kde_te / te_rate) : 0.0f;
        float d_s = (tr_rate > 0.0f) ? (kde_tr / tr_rate) : 0.0f;

        float p_hs = kdw * p_y / (kde_tr + 1e-8f);
        p_hs = fminf(fmaxf(p_hs, 0.0f), 1.0f);
        term = p_hs * (d_t - d_s);
    }

    red[tid] = (double)term;
    __syncthreads();
    #pragma unroll
    for (int o = 64; o > 0; o >>= 1) {
        if (tid < o) red[tid] += red[tid + o];
        __syncthreads();
    }
    if (tid == 0) g_partial[bin * NCHB + blockIdx.x] = red[0];
}

// ---------------------------------------------------------------------------
__global__ __launch_bounds__(512) void ec_final(float* __restrict__ out) {
    __shared__ double sbin[16];
    int t = threadIdx.x, w = t >> 5, lane = t & 31;
    if (w < NBINS) {
        double s = 0.0;
        for (int c = lane; c < NCHB; c += 32) s += g_partial[w * NCHB + c];
        #pragma unroll
        for (int o = 16; o; o >>= 1) s += __shfl_xor_sync(0xffffffffu, s, o);
        if (lane == 0) {
            double integral = s * (100.0 / (double)NMC);
            float te = (float)g_hte[w] * (1.0f / (float)NTE);
            sbin[w] = (te > 0.0f) ? (double)te * fabs(integral) : 0.0;
        }
    }
    __syncthreads();
    if (t == 0) {
        double ec = 0.0;
        for (int b = 0; b < NBINS; b++) ec += sbin[b];
        out[0] = (float)ec;
    }
}

// ---------------------------------------------------------------------------
extern "C" void kernel_launch(void* const* d_in, const int* in_sizes, int n_in,
                              void* d_out, int out_size) {
    const float *batch_x = nullptr, *train_probs = nullptr, *test_probs = nullptr;
    const float *train_x = nullptr, *test_x = nullptr, *W = nullptr, *bvec = nullptr, *mc = nullptr;
    const int   *y = nullptr, *pred = nullptr;

    for (int i = 0; i < n_in; i++) {
        int s = in_sizes[i];
        void* p = d_in[i];
        switch (s) {
            case 2048:   batch_x = (const float*)p; break;
            case 1024:   if (!y) y = (const int*)p; else pred = (const int*)p; break;
            case 20000:  if (!train_probs) train_probs = (const float*)p;
                         else test_x = (const float*)p; break;
            case 10000:  test_probs = (const float*)p; break;
            case 40000:  train_x = (const float*)p; break;
            case 20:     W = (const float*)p; break;
            case 10:     bvec = (const float*)p; break;
            case 300000: mc = (const float*)p; break;
            default: break;
        }
    }

    ec_prep<<<1, 1024>>>(train_probs, test_probs, y, pred);
    ec_sort<<<18, STHREADS>>>((const float2*)train_x, (const float2*)test_x,
                              (const float2*)batch_x, y, pred, (const float2*)mc, W, bvec);
    ec_plan<<<1, 256>>>();
    ec_plan2<<<NQWMAX, 32>>>();
    ec_phaseA<<<NBLKA, 128>>>();
    ec_phaseB<<<dim3(NCHB, NBINS), 128>>>();
    ec_final<<<1, 512>>>((float*)d_out);
}

// round 8
// speedup vs baseline: 9.2770x; 1.4707x over previous
#include <cuda_runtime.h>
#include <math.h>

#define NBINS   15
#define NTR     20000
#define NTE     10000
#define NBATCH  1024
#define NMC     10000
#define NCLS    10
#define NPTS_TOT (NTR + NTE + NBATCH)

#define GRIDW   16
#define CELLSZ  0.75f
#define INVCELL (1.0f / 0.75f)
#define DOMLO   (-6.0f)
#define RC      2.0f

#define CEXP       8.014972449383130f
#define KDE_NORM_F 0.56548667764616278f

#define NQWMAX  704
#define NSLOT   64           // CHPTS*NSLOT >= NPTS_TOT
#define CHPTS   512
#define NBLKA   592
#define NCHB    79
#define MAXROWS 16

#define NPREP   30
#define PTHREADS 512

#define STHREADS 1024
#define SWARPS   32

__device__ int    g_htr_part[NPREP][NBINS];
__device__ int    g_hte_part[NPREP][NBINS];
__device__ int    g_c_part[NPREP];
__device__ int    g_htr[NBINS], g_hte[NBINS], g_c;
__device__ int    g_qn[NBINS];
__device__ int    g_cs_p[3][257];
__device__ int    g_wq_bin[NQWMAX];
__device__ int    g_wq_first[NBINS];
__device__ int    g_ntask, g_task_ctr;
__device__ int    g_qw_span[NQWMAX];
__device__ int    g_qw_nrows[NQWMAX];
__device__ int4   g_qw_rowA[NQWMAX * MAXROWS];   // {cum, jtr0, jte0, jb0}
__device__ int4   g_qw_rowB[NQWMAX * MAXROWS];   // {Ltr, Lte, Lb, 0}
__device__ float4 g_spts[NPTS_TOT];
__device__ float4 g_qs[NBINS * NMC];
__device__ float4 g_A[NSLOT][NQWMAX * 32];
__device__ double g_partial[NBINS * NCHB];

__device__ __forceinline__ float ex2f(float x) {
    float r;
    asm("ex2.approx.ftz.f32 %0, %1;" : "=f"(r) : "f"(x));
    return r;
}
__device__ __forceinline__ float bin_lo(int b) { return (float)b * (1.0f / 15.0f); }
__device__ __forceinline__ float bin_hi(int b) { return (b == NBINS - 1) ? 1.0f : (float)(b + 1) * (1.0f / 15.0f); }

__device__ __forceinline__ int cell_of(float x, float y) {
    int cx = min(max((int)floorf((x - DOMLO) * INVCELL), 0), GRIDW - 1);
    int cy = min(max((int)floorf((y - DOMLO) * INVCELL), 0), GRIDW - 1);
    return cy * GRIDW + cx;
}
__device__ __forceinline__ int cell_of_snake(float x, float y) {
    int cx = min(max((int)floorf((x - DOMLO) * INVCELL), 0), GRIDW - 1);
    int cy = min(max((int)floorf((y - DOMLO) * INVCELL), 0), GRIDW - 1);
    if (cy & 1) cx = GRIDW - 1 - cx;
    return cy * GRIDW + cx;
}

// ---------------------------------------------------------------------------
// Prep: gridded partial histograms, fixed slots (no atomics, no pre-zero)
// ---------------------------------------------------------------------------
__global__ __launch_bounds__(PTHREADS) void ec_prep(const float* __restrict__ tp,
                                                    const float* __restrict__ sp,
                                                    const int* __restrict__ y,
                                                    const int* __restrict__ pred) {
    __shared__ int h1[NBINS], h2[NBINS], sc;
    int t = threadIdx.x, blk = blockIdx.x;
    if (t < NBINS) { h1[t] = 0; h2[t] = 0; }
    if (t == 0) sc = 0;
    __syncthreads();

    int gs = NPREP * PTHREADS;
    int g  = blk * PTHREADS + t;

    int c = 0;
    for (int i = g; i < NBATCH; i += gs) c += (y[i] == pred[i]) ? 1 : 0;
    #pragma unroll
    for (int o = 16; o; o >>= 1) c += __shfl_xor_sync(0xffffffffu, c, o);
    if ((t & 31) == 0 && c) atomicAdd(&sc, c);

    for (int i = g; i < NTR; i += gs) {
        float p = tp[i];
        #pragma unroll
        for (int b = 0; b < NBINS; b++)
            if (p > bin_lo(b) && p <= bin_hi(b)) atomicAdd(&h1[b], 1);
    }
    for (int i = g; i < NTE; i += gs) {
        float p = sp[i];
        #pragma unroll
        for (int b = 0; b < NBINS; b++)
            if (p > bin_lo(b) && p <= bin_hi(b)) atomicAdd(&h2[b], 1);
    }
    __syncthreads();
    if (t < NBINS) { g_htr_part[blk][t] = h1[t]; g_hte_part[blk][t] = h2[t]; }
    if (t == 0) g_c_part[blk] = sc;
}

// ---------------------------------------------------------------------------
// Deterministic stable counting sort + inline softmax filter for queries
// ---------------------------------------------------------------------------
__global__ __launch_bounds__(STHREADS) void ec_sort(
    const float2* __restrict__ train, const float2* __restrict__ test,
    const float2* __restrict__ batch, const int* __restrict__ y,
    const int* __restrict__ pred, const float2* __restrict__ mc,
    const float* __restrict__ W, const float* __restrict__ bvec)
{
    __shared__ int  hist[257 * SWARPS];
    __shared__ int  s_tot[257];
    __shared__ int  s_cs[258];
    __shared__ unsigned char s_flag[NMC];

    int task = blockIdx.x;
    const float2* src; int N; float4* dst;
    bool isq = false, isb = false;
    int bin = 0;
    if      (task == 0) { src = train; N = NTR;    dst = g_spts; }
    else if (task == 1) { src = test;  N = NTE;    dst = g_spts + NTR; }
    else if (task == 2) { src = batch; N = NBATCH; dst = g_spts + NTR + NTE; isb = true; }
    else { bin = task - 3; src = mc + bin * NMC; N = NMC; dst = g_qs + bin * NMC; isq = true; }

    int t = threadIdx.x, w = t >> 5, lane = t & 31;
    unsigned lmask = (1u << lane) - 1u;

    for (int i = t; i < 257 * SWARPS; i += STHREADS) hist[i] = 0;
    __syncthreads();

    int iters = (N + STHREADS - 1) / STHREADS;
    float blo = bin_lo(bin), bhi = bin_hi(bin);

    for (int k = 0; k < iters; k++) {
        int i = k * STHREADS + t;
        int c = 256;
        if (i < N) {
            float2 p = src[i];
            if (isq) {
                float l[NCLS];
                float m = -1.0e30f;
                #pragma unroll
                for (int cc = 0; cc < NCLS; cc++) {
                    l[cc] = fmaf(p.x, __ldg(W + cc), fmaf(p.y, __ldg(W + NCLS + cc), __ldg(bvec + cc)));
                    m = fmaxf(m, l[cc]);
                }
                float ssum = 0.0f;
                #pragma unroll
                for (int cc = 0; cc < NCLS; cc++) ssum += __expf(l[cc] - m);
                float hat = 1.0f / ssum;
                int f = (hat >= blo && hat <= bhi) ? 1 : 0;
                s_flag[i] = (unsigned char)f;
                c = f ? cell_of_snake(p.x, p.y) : 256;
            }
            else if (isb) c = (y[i] != pred[i]) ? 256 : cell_of(p.x, p.y);
            else          c = cell_of(p.x, p.y);
        }
        unsigned m = __match_any_sync(0xffffffffu, c);
        int leader = __ffs(m) - 1;
        if (lane == leader) hist[c * SWARPS + w] += __popc(m);
    }
    __syncthreads();

    for (int c = w; c < 257; c += SWARPS) {
        int v = hist[c * SWARPS + lane];
        int incl = v;
        #pragma unroll
        for (int o = 1; o < 32; o <<= 1) {
            int n = __shfl_up_sync(0xffffffffu, incl, o);
            if (lane >= o) incl += n;
        }
        hist[c * SWARPS + lane] = incl - v;
        if (lane == 31) s_tot[c] = incl;
    }
    __syncthreads();
    if (t == 0) {
        int run = 0;
        for (int c = 0; c < 256; c++) { s_cs[c] = run; run += s_tot[c]; }
        s_cs[256] = run;
        if (isq) g_qn[bin] = run;
    }
    __syncthreads();
    if (!isq) {
        if (t < 256) g_cs_p[task][t] = s_cs[t];
        if (t == 0)  g_cs_p[task][256] = s_cs[256];
    }

    for (int k = 0; k < iters; k++) {
        int i = k * STHREADS + t;
        int c = 256;
        float2 p = make_float2(0.0f, 0.0f);
        if (i < N) {
            p = src[i];
            if (isq)      c = s_flag[i] ? cell_of_snake(p.x, p.y) : 256;
            else if (isb) c = (y[i] != pred[i]) ? 256 : cell_of(p.x, p.y);
            else          c = cell_of(p.x, p.y);
        }
        unsigned m = __match_any_sync(0xffffffffu, c);
        int leader = __ffs(m) - 1;
        int r = 0;
        if (lane == leader) {
            r = hist[c * SWARPS + w];
            hist[c * SWARPS + w] = r + __popc(m);
        }
        r = __shfl_sync(0xffffffffu, r, leader);
        if (c < 256) {
            int off = s_cs[c] + r + __popc(m & lmask);
            float s2 = p.x * p.x + p.y * p.y;
            dst[off] = isq ? make_float4(p.x, p.y, -CEXP * s2, 0.0f)
                           : make_float4(2.0f * CEXP * p.x, 2.0f * CEXP * p.y, -CEXP * s2, 0.0f);
        }
    }
}

// ---------------------------------------------------------------------------
// Fused plan: per-qw geometry (one 32-thread block per qw), local bin prefix;
// block 0 additionally folds prep partials + resets the task counter.
// ---------------------------------------------------------------------------
__global__ __launch_bounds__(32) void ec_plan() {
    int lane = threadIdx.x;
    int qw = blockIdx.x;

    // local exclusive prefix of warp counts per bin (lanes 0..14 hold bins)
    int qnb = (lane < NBINS) ? g_qn[lane] : 0;
    int nw  = (qnb + 31) / 32;
    int incl = nw;
    #pragma unroll
    for (int o = 1; o < 32; o <<= 1) {
        int n = __shfl_up_sync(0xffffffffu, incl, o);
        if (lane >= o) incl += n;
    }
    int ex  = incl - nw;
    int tot = __shfl_sync(0xffffffffu, incl, NBINS - 1);

    if (qw == 0) {
        if (lane == 0) { g_ntask = tot * NSLOT; g_task_ctr = 0; }
        if (lane < NBINS) {
            g_wq_first[lane] = ex;
            int s1 = 0, s2 = 0;
            for (int p = 0; p < NPREP; p++) { s1 += g_htr_part[p][lane]; s2 += g_hte_part[p][lane]; }
            g_htr[lane] = s1; g_hte[lane] = s2;
        }
        if (lane == 31) {
            int s = 0;
            for (int p = 0; p < NPREP; p++) s += g_c_part[p];
            g_c = s;
        }
    }

    if (qw >= tot) return;

    // find bin for this qw
    int bin = 0;
    #pragma unroll
    for (int b = 0; b < NBINS; b++) {
        int fb = __shfl_sync(0xffffffffu, ex, b);
        if (qw >= fb) bin = b;
    }
    int first = __shfl_sync(0xffffffffu, ex, bin);
    if (lane == 0) g_wq_bin[qw] = bin;

    int lqw = qw - first;
    int qn  = __shfl_sync(0xffffffffu, qnb, bin);
    int qi  = lqw * 32 + lane;
    bool valid = qi < qn;
    float4 q = valid ? g_qs[bin * NMC + qi] : make_float4(0.0f, 0.0f, 0.0f, 0.0f);

    float xmn = valid ? q.x : 1.0e30f, xmx = valid ? q.x : -1.0e30f;
    float ymn = valid ? q.y : 1.0e30f, ymx = valid ? q.y : -1.0e30f;
    #pragma unroll
    for (int o = 16; o; o >>= 1) {
        xmn = fminf(xmn, __shfl_xor_sync(0xffffffffu, xmn, o));
        xmx = fmaxf(xmx, __shfl_xor_sync(0xffffffffu, xmx, o));
        ymn = fminf(ymn, __shfl_xor_sync(0xffffffffu, ymn, o));
        ymx = fmaxf(ymx, __shfl_xor_sync(0xffffffffu, ymx, o));
    }

    if (lane == 0) {
        int cy0 = min(max((int)floorf((ymn - RC - DOMLO) * INVCELL), 0), GRIDW - 1);
        int cy1 = min(max((int)floorf((ymx + RC - DOMLO) * INVCELL), 0), GRIDW - 1);
        int cum = 0, nr = 0;
        for (int cy = cy0; cy <= cy1; cy++) {
            float cyl = DOMLO + cy * CELLSZ, cyh = cyl + CELLSZ;
            float dyv = fmaxf(0.0f, fmaxf(cyl - ymx, ymn - cyh));
            float d2 = RC * RC - dyv * dyv;
            if (d2 <= 0.0f) continue;
            float dxv = sqrtf(d2);
            int cx0 = min(max((int)floorf((xmn - dxv - DOMLO) * INVCELL), 0), GRIDW - 1);
            int cx1 = min(max((int)floorf((xmx + dxv - DOMLO) * INVCELL), 0), GRIDW - 1);
            int ca = cy * GRIDW + cx0, cb = cy * GRIDW + cx1 + 1;
            int jtr0 = g_cs_p[0][ca], Ltr = g_cs_p[0][cb] - jtr0;
            int jte0 = g_cs_p[1][ca], Lte = g_cs_p[1][cb] - jte0;
            int jb0  = g_cs_p[2][ca], Lb  = g_cs_p[2][cb] - jb0;
            if (Ltr + Lte + Lb > 0) {
                g_qw_rowA[qw * MAXROWS + nr] = make_int4(cum, jtr0, jte0, jb0);
                g_qw_rowB[qw * MAXROWS + nr] = make_int4(Ltr, Lte, Lb, 0);
                cum += Ltr + Lte + Lb;
                nr++;
            }
        }
        g_qw_nrows[qw] = nr;
        g_qw_span[qw]  = cum;
    }
}

// ---------------------------------------------------------------------------
// Phase A: fine-grained dynamic stealing over precomputed span chunks
// ---------------------------------------------------------------------------
__device__ __forceinline__ float kde_span(const float4* __restrict__ pts,
                                          int j0, int j1, float qx, float qy, float qc, float acc)
{
    int j = j0;
    for (; j + 4 <= j1; j += 4) {
        float4 p0 = __ldg(pts + j);
        float4 p1 = __ldg(pts + j + 1);
        float4 p2 = __ldg(pts + j + 2);
        float4 p3 = __ldg(pts + j + 3);
        float t0 = fmaf(p0.x, qx, fmaf(p0.y, qy, p0.z)) + qc;
        float t1 = fmaf(p1.x, qx, fmaf(p1.y, qy, p1.z)) + qc;
        float t2 = fmaf(p2.x, qx, fmaf(p2.y, qy, p2.z)) + qc;
        float t3 = fmaf(p3.x, qx, fmaf(p3.y, qy, p3.z)) + qc;
        acc += ex2f(t0); acc += ex2f(t1); acc += ex2f(t2); acc += ex2f(t3);
    }
    for (; j < j1; j++) {
        float4 p = __ldg(pts + j);
        acc += ex2f(fmaf(p.x, qx, fmaf(p.y, qy, p.z)) + qc);
    }
    return acc;
}

__global__ __launch_bounds__(256) void ec_phaseA()
{
    const int lane = threadIdx.x & 31;
    const int ntask = g_ntask;

    int   cached_qw = -1;
    float qx = 0.0f, qy = 0.0f, qc = -1.0e30f;

    while (true) {
        int tk = 0;
        if (lane == 0) tk = atomicAdd(&g_task_ctr, 1);
        tk = __shfl_sync(0xffffffffu, tk, 0);
        if (tk >= ntask) return;

        int qw = tk >> 6, slot = tk & (NSLOT - 1);
        int span = g_qw_span[qw];
        int lo = slot * CHPTS;
        if (lo >= span) continue;
        int hi = min(lo + CHPTS, span);

        if (qw != cached_qw) {
            cached_qw = qw;
            int bin = g_wq_bin[qw];
            int lqw = qw - g_wq_first[bin];
            int qn  = g_qn[bin];
            int qi  = lqw * 32 + lane;
            bool valid = qi < qn;
            float4 q = valid ? g_qs[bin * NMC + qi] : make_float4(0.0f, 0.0f, -1.0e30f, 0.0f);
            qx = q.x; qy = q.y; qc = q.z;
        }

        int nrows = g_qw_nrows[qw];
        float st = 0.0f, se = 0.0f, sb = 0.0f;

        for (int r = 0; r < nrows; r++) {
            int4 A = g_qw_rowA[qw * MAXROWS + r];
            if (A.x >= hi) break;
            int4 B = g_qw_rowB[qw * MAXROWS + r];
            int rowEnd = A.x + B.x + B.y + B.z;
            if (rowEnd <= lo) continue;

            int seg0 = A.x;
            {
                int a = max(lo - seg0, 0), b = min(hi - seg0, B.x);
                if (b > a) st = kde_span(g_spts, A.y + a, A.y + b, qx, qy, qc, st);
                seg0 += B.x;
            }
            {
                int a = max(lo - seg0, 0), b = min(hi - seg0, B.y);
                if (b > a) se = kde_span(g_spts + NTR, A.z + a, A.z + b, qx, qy, qc, se);
                seg0 += B.y;
            }
            {
                int a = max(lo - seg0, 0), b = min(hi - seg0, B.z);
                if (b > a) sb = kde_span(g_spts + NTR + NTE, A.w + a, A.w + b, qx, qy, qc, sb);
            }
        }

        g_A[slot][qw * 32 + lane] = make_float4(st, se, sb, 0.0f);
    }
}

// ---------------------------------------------------------------------------
// Phase B: fold slots in fixed order + epilogue + fixed-slot reduction
// ---------------------------------------------------------------------------
__global__ __launch_bounds__(128) void ec_phaseB()
{
    __shared__ double red[128];
    int tid = threadIdx.x;
    int bin = blockIdx.y;
    int k   = blockIdx.x * 128 + tid;

    float term = 0.0f;
    if (k < g_qn[bin]) {
        int qw  = g_wq_first[bin] + (k >> 5);
        int gqi = qw * 32 + (k & 31);
        int nslots = min((g_qw_span[qw] + CHPTS - 1) / CHPTS, NSLOT);
        float st = 0.0f, se = 0.0f, sb = 0.0f;
        for (int s = 0; s < nslots; s++) {
            float4 a = g_A[s][gqi];
            st += a.x; se += a.y; sb += a.z;
        }

        float cnt     = (float)g_c;
        float tr_rate = (float)g_htr[bin] * (1.0f / (float)NTR);
        float te_rate = (float)g_hte[bin] * (1.0f / (float)NTE);

        float kde_tr = st * (1.0f / ((float)NTR * KDE_NORM_F));
        float kde_te = se * (1.0f / ((float)NTE * KDE_NORM_F));
        float kdw    = sb / (fmaxf(cnt, 1.0f) * KDE_NORM_F);
        float p_y    = cnt * (1.0f / (float)NBATCH);

        float d_t = (te_rate > 0.0f) ? (kde_te / te_rate) : 0.0f;
        float d_s = (tr_rate > 0.0f) ? (kde_tr / tr_rate) : 0.0f;

        float p_hs = kdw * p_y / (kde_tr + 1e-8f);
        p_hs = fminf(fmaxf(p_hs, 0.0f), 1.0f);
        term = p_hs * (d_t - d_s);
    }

    red[tid] = (double)term;
    __syncthreads();
    #pragma unroll
    for (int o = 64; o > 0; o >>= 1) {
        if (tid < o) red[tid] += red[tid + o];
        __syncthreads();
    }
    if (tid == 0) g_partial[bin * NCHB + blockIdx.x] = red[0];
}

// ---------------------------------------------------------------------------
__global__ __launch_bounds__(512) void ec_final(float* __restrict__ out) {
    __shared__ double sbin[16];
    int t = threadIdx.x, w = t >> 5, lane = t & 31;
    if (w < NBINS) {
        double s = 0.0;
        for (int c = lane; c < NCHB; c += 32) s += g_partial[w * NCHB + c];
        #pragma unroll
        for (int o = 16; o; o >>= 1) s += __shfl_xor_sync(0xffffffffu, s, o);
        if (lane == 0) {
            double integral = s * (100.0 / (double)NMC);
            float te = (float)g_hte[w] * (1.0f / (float)NTE);
            sbin[w] = (te > 0.0f) ? (double)te * fabs(integral) : 0.0;
        }
    }
    __syncthreads();
    if (t == 0) {
        double ec = 0.0;
        for (int b = 0; b < NBINS; b++) ec += sbin[b];
        out[0] = (float)ec;
    }
}

// ---------------------------------------------------------------------------
extern "C" void kernel_launch(void* const* d_in, const int* in_sizes, int n_in,
                              void* d_out, int out_size) {
    const float *batch_x = nullptr, *train_probs = nullptr, *test_probs = nullptr;
    const float *train_x = nullptr, *test_x = nullptr, *W = nullptr, *bvec = nullptr, *mc = nullptr;
    const int   *y = nullptr, *pred = nullptr;

    for (int i = 0; i < n_in; i++) {
        int s = in_sizes[i];
        void* p = d_in[i];
        switch (s) {
            case 2048:   batch_x = (const float*)p; break;
            case 1024:   if (!y) y = (const int*)p; else pred = (const int*)p; break;
            case 20000:  if (!train_probs) train_probs = (const float*)p;
                         else test_x = (const float*)p; break;
            case 10000:  test_probs = (const float*)p; break;
            case 40000:  train_x = (const float*)p; break;
            case 20:     W = (const float*)p; break;
            case 10:     bvec = (const float*)p; break;
            case 300000: mc = (const float*)p; break;
            default: break;
        }
    }

    ec_prep<<<NPREP, PTHREADS>>>(train_probs, test_probs, y, pred);
    ec_sort<<<18, STHREADS>>>((const float2*)train_x, (const float2*)test_x,
                              (const float2*)batch_x, y, pred, (const float2*)mc, W, bvec);
    ec_plan<<<NQWMAX, 32>>>();
    ec_phaseA<<<NBLKA, 256>>>();
    ec_phaseB<<<dim3(NCHB, NBINS), 128>>>();
    ec_final<<<1, 512>>>((float*)d_out);
}